// round 1
// baseline (speedup 1.0000x reference)
#include <cuda_runtime.h>
#include <math.h>

// ---------------- problem constants ----------------
#define E_DIM  1024
#define H_NUM  16
#define DK_    64
#define B_SZ   2
#define S_LEN  2048
#define M_TOK  (B_SZ * S_LEN)       // 4096 tokens
#define N_QKV  (3 * E_DIM)          // 3072
#define K_DIM  1024

// ---------------- device scratch (alloc-free) ----------------
__device__ float g_q[B_SZ * H_NUM * S_LEN * DK_];     // [B,H,S,dk]
__device__ float g_k[B_SZ * H_NUM * S_LEN * DK_];
__device__ float g_v[B_SZ * H_NUM * S_LEN * DK_];
__device__ float g_attn[M_TOK * E_DIM];               // [B,S,E] attention output
__device__ float g_proj[M_TOK * E_DIM];               // [B,S,E] combine-proj output (+bias)

// ======================================================================
// GEMM1: qkv = x @ w_qkv^T, M=4096, N=3072, K=1024
// C[m][n] = sum_k A[m][k] * W[n][k]
// Epilogue scatters into g_q / g_k / g_v with [B,H,S,dk] layout.
// Tile: BM=BN=128, BK=16, 256 threads, 8x8 register blocking.
// ======================================================================
__global__ __launch_bounds__(256) void gemm_qkv(const float* __restrict__ A,
                                                const float* __restrict__ W)
{
    __shared__ float As[16][128];
    __shared__ float Bs[16][128];
    const int tid = threadIdx.x;
    const int tx = tid & 15, ty = tid >> 4;
    const int m0 = blockIdx.y * 128;
    const int n0 = blockIdx.x * 128;

    float acc[8][8];
#pragma unroll
    for (int i = 0; i < 8; i++)
#pragma unroll
        for (int j = 0; j < 8; j++) acc[i][j] = 0.f;

    for (int k0 = 0; k0 < K_DIM; k0 += 16) {
#pragma unroll
        for (int it = 0; it < 2; it++) {
            int idx = tid + it * 256;          // 0..511
            int r = idx >> 2;                  // 0..127
            int c = (idx & 3) << 2;            // 0,4,8,12
            float4 av = *(const float4*)&A[(size_t)(m0 + r) * K_DIM + k0 + c];
            As[c + 0][r] = av.x; As[c + 1][r] = av.y;
            As[c + 2][r] = av.z; As[c + 3][r] = av.w;
            float4 wv = *(const float4*)&W[(size_t)(n0 + r) * K_DIM + k0 + c];
            Bs[c + 0][r] = wv.x; Bs[c + 1][r] = wv.y;
            Bs[c + 2][r] = wv.z; Bs[c + 3][r] = wv.w;
        }
        __syncthreads();
#pragma unroll
        for (int k = 0; k < 16; k++) {
            float a_[8], b_[8];
            *(float4*)&a_[0] = *(const float4*)&As[k][ty * 8];
            *(float4*)&a_[4] = *(const float4*)&As[k][ty * 8 + 4];
            *(float4*)&b_[0] = *(const float4*)&Bs[k][tx * 8];
            *(float4*)&b_[4] = *(const float4*)&Bs[k][tx * 8 + 4];
#pragma unroll
            for (int i = 0; i < 8; i++)
#pragma unroll
                for (int j = 0; j < 8; j++) acc[i][j] += a_[i] * b_[j];
        }
        __syncthreads();
    }

    // epilogue: column block n0+tx*8 .. +7 lies within one (which, head) pair
    const int nb = n0 + tx * 8;
    const int which = nb >> 10;          // 0=q,1=k,2=v
    const int h = (nb >> 6) & 15;
    const int d0 = nb & 63;
    float* dst = (which == 0) ? g_q : (which == 1) ? g_k : g_v;
#pragma unroll
    for (int i = 0; i < 8; i++) {
        int m = m0 + ty * 8 + i;
        int b = m >> 11, s = m & 2047;
        size_t base = (((size_t)b * H_NUM + h) * S_LEN + s) * DK_ + d0;
        float4 o0 = make_float4(acc[i][0], acc[i][1], acc[i][2], acc[i][3]);
        float4 o1 = make_float4(acc[i][4], acc[i][5], acc[i][6], acc[i][7]);
        *(float4*)&dst[base] = o0;
        *(float4*)&dst[base + 4] = o1;
    }
}

// ======================================================================
// GEMM2: proj = attn @ w_comb^T + b_comb, M=4096, N=1024, K=1024
// ======================================================================
__global__ __launch_bounds__(256) void gemm_out(const float* __restrict__ W,
                                                const float* __restrict__ bias)
{
    const float* A = g_attn;
    __shared__ float As[16][128];
    __shared__ float Bs[16][128];
    const int tid = threadIdx.x;
    const int tx = tid & 15, ty = tid >> 4;
    const int m0 = blockIdx.y * 128;
    const int n0 = blockIdx.x * 128;

    float acc[8][8];
#pragma unroll
    for (int i = 0; i < 8; i++)
#pragma unroll
        for (int j = 0; j < 8; j++) acc[i][j] = 0.f;

    for (int k0 = 0; k0 < K_DIM; k0 += 16) {
#pragma unroll
        for (int it = 0; it < 2; it++) {
            int idx = tid + it * 256;
            int r = idx >> 2;
            int c = (idx & 3) << 2;
            float4 av = *(const float4*)&A[(size_t)(m0 + r) * K_DIM + k0 + c];
            As[c + 0][r] = av.x; As[c + 1][r] = av.y;
            As[c + 2][r] = av.z; As[c + 3][r] = av.w;
            float4 wv = *(const float4*)&W[(size_t)(n0 + r) * K_DIM + k0 + c];
            Bs[c + 0][r] = wv.x; Bs[c + 1][r] = wv.y;
            Bs[c + 2][r] = wv.z; Bs[c + 3][r] = wv.w;
        }
        __syncthreads();
#pragma unroll
        for (int k = 0; k < 16; k++) {
            float a_[8], b_[8];
            *(float4*)&a_[0] = *(const float4*)&As[k][ty * 8];
            *(float4*)&a_[4] = *(const float4*)&As[k][ty * 8 + 4];
            *(float4*)&b_[0] = *(const float4*)&Bs[k][tx * 8];
            *(float4*)&b_[4] = *(const float4*)&Bs[k][tx * 8 + 4];
#pragma unroll
            for (int i = 0; i < 8; i++)
#pragma unroll
                for (int j = 0; j < 8; j++) acc[i][j] += a_[i] * b_[j];
        }
        __syncthreads();
    }

    const int n = n0 + tx * 8;
    float bb[8];
#pragma unroll
    for (int j = 0; j < 8; j++) bb[j] = bias[n + j];
#pragma unroll
    for (int i = 0; i < 8; i++) {
        int m = m0 + ty * 8 + i;
        float4 o0 = make_float4(acc[i][0] + bb[0], acc[i][1] + bb[1],
                                acc[i][2] + bb[2], acc[i][3] + bb[3]);
        float4 o1 = make_float4(acc[i][4] + bb[4], acc[i][5] + bb[5],
                                acc[i][6] + bb[6], acc[i][7] + bb[7]);
        *(float4*)&g_proj[(size_t)m * E_DIM + n] = o0;
        *(float4*)&g_proj[(size_t)m * E_DIM + n + 4] = o1;
    }
}

// ======================================================================
// Flash attention (fp32): per block one (b, h, 64-row Q tile).
// BQ=BKV=64, dk=64. 256 threads; 4x4 register tile per thread.
// Online softmax: row stats via warp shuffles (16-lane row groups).
// Output written directly in [B,S,E] layout into g_attn.
// Dynamic smem: Qs[64][68] Ks[64][65] Vs[64][68] Ps[64][68] m[64] l[64]
// ======================================================================
#define QS_LD 68
#define KS_LD 65
#define VS_LD 68
#define PS_LD 68
#define FLASH_SMEM_FLOATS (64*QS_LD + 64*KS_LD + 64*VS_LD + 64*PS_LD + 128)
#define FLASH_SMEM_BYTES  (FLASH_SMEM_FLOATS * 4)

__global__ __launch_bounds__(256) void flash_attn()
{
    extern __shared__ float sm[];
    float* Qs   = sm;
    float* Ks   = Qs + 64 * QS_LD;
    float* Vs   = Ks + 64 * KS_LD;
    float* Ps   = Vs + 64 * VS_LD;
    float* mrow = Ps + 64 * PS_LD;
    float* lrow = mrow + 64;

    const int tid = threadIdx.x;
    const int tx = tid & 15, ty = tid >> 4;
    const int b = blockIdx.z, h = blockIdx.y;
    const int q0 = blockIdx.x * 64;
    const size_t hoff = ((size_t)(b * H_NUM + h)) * S_LEN * DK_;

    // load Q tile (pre-scaled by 1/sqrt(dk) = 0.125)
#pragma unroll
    for (int it = 0; it < 4; it++) {
        int idx = tid + it * 256;
        int r = idx >> 4, c = (idx & 15) << 2;
        float4 v = *(const float4*)&g_q[hoff + (size_t)(q0 + r) * DK_ + c];
        v.x *= 0.125f; v.y *= 0.125f; v.z *= 0.125f; v.w *= 0.125f;
        *(float4*)&Qs[r * QS_LD + c] = v;
    }
    if (tid < 64) { mrow[tid] = -1e30f; lrow[tid] = 0.f; }

    float acc[4][4];
#pragma unroll
    for (int i = 0; i < 4; i++)
#pragma unroll
        for (int j = 0; j < 4; j++) acc[i][j] = 0.f;
    __syncthreads();

    for (int kt = 0; kt < S_LEN / 64; kt++) {
        const int k0 = kt * 64;
        // load K (scalar stores, pad 65) and V (float4, pad 68)
#pragma unroll
        for (int it = 0; it < 4; it++) {
            int idx = tid + it * 256;
            int r = idx >> 4, c = (idx & 15) << 2;
            float4 kv = *(const float4*)&g_k[hoff + (size_t)(k0 + r) * DK_ + c];
            Ks[r * KS_LD + c + 0] = kv.x; Ks[r * KS_LD + c + 1] = kv.y;
            Ks[r * KS_LD + c + 2] = kv.z; Ks[r * KS_LD + c + 3] = kv.w;
            float4 vv = *(const float4*)&g_v[hoff + (size_t)(k0 + r) * DK_ + c];
            *(float4*)&Vs[r * VS_LD + c] = vv;
        }
        __syncthreads();

        // ---- S = (Q*0.125) @ K^T ----
        float s[4][4];
#pragma unroll
        for (int i = 0; i < 4; i++)
#pragma unroll
            for (int j = 0; j < 4; j++) s[i][j] = 0.f;

        for (int d0 = 0; d0 < DK_; d0 += 4) {
            float a_[4][4];
#pragma unroll
            for (int i = 0; i < 4; i++) {
                float4 t = *(const float4*)&Qs[(ty * 4 + i) * QS_LD + d0];
                a_[i][0] = t.x; a_[i][1] = t.y; a_[i][2] = t.z; a_[i][3] = t.w;
            }
#pragma unroll
            for (int dd = 0; dd < 4; dd++) {
                float bk[4];
#pragma unroll
                for (int j = 0; j < 4; j++) bk[j] = Ks[(tx * 4 + j) * KS_LD + d0 + dd];
#pragma unroll
                for (int i = 0; i < 4; i++)
#pragma unroll
                    for (int j = 0; j < 4; j++) s[i][j] += a_[i][dd] * bk[j];
            }
        }

        // ---- online softmax stats (per row, 16-lane shuffle groups) ----
#pragma unroll
        for (int i = 0; i < 4; i++) {
            const int row = ty * 4 + i;
            float rm = fmaxf(fmaxf(s[i][0], s[i][1]), fmaxf(s[i][2], s[i][3]));
            rm = fmaxf(rm, __shfl_xor_sync(0xffffffffu, rm, 1));
            rm = fmaxf(rm, __shfl_xor_sync(0xffffffffu, rm, 2));
            rm = fmaxf(rm, __shfl_xor_sync(0xffffffffu, rm, 4));
            rm = fmaxf(rm, __shfl_xor_sync(0xffffffffu, rm, 8));
            float mo = mrow[row];
            float mn = fmaxf(mo, rm);
            float sum = 0.f;
#pragma unroll
            for (int j = 0; j < 4; j++) {
                float p = __expf(s[i][j] - mn);
                s[i][j] = p;
                sum += p;
            }
            sum += __shfl_xor_sync(0xffffffffu, sum, 1);
            sum += __shfl_xor_sync(0xffffffffu, sum, 2);
            sum += __shfl_xor_sync(0xffffffffu, sum, 4);
            sum += __shfl_xor_sync(0xffffffffu, sum, 8);
            float sc = __expf(mo - mn);
#pragma unroll
            for (int j = 0; j < 4; j++) acc[i][j] *= sc;
            if (tx == 0) {
                mrow[row] = mn;
                lrow[row] = lrow[row] * sc + sum;
            }
            // store P row chunk
            *(float4*)&Ps[row * PS_LD + tx * 4] =
                make_float4(s[i][0], s[i][1], s[i][2], s[i][3]);
        }
        __syncwarp();

        // ---- O += P @ V ----
        for (int j0 = 0; j0 < 64; j0 += 4) {
            float p_[4][4];
#pragma unroll
            for (int i = 0; i < 4; i++) {
                float4 t = *(const float4*)&Ps[(ty * 4 + i) * PS_LD + j0];
                p_[i][0] = t.x; p_[i][1] = t.y; p_[i][2] = t.z; p_[i][3] = t.w;
            }
#pragma unroll
            for (int jj = 0; jj < 4; jj++) {
                float4 v4 = *(const float4*)&Vs[(j0 + jj) * VS_LD + tx * 4];
                float v_[4] = {v4.x, v4.y, v4.z, v4.w};
#pragma unroll
                for (int i = 0; i < 4; i++)
#pragma unroll
                    for (int j = 0; j < 4; j++) acc[i][j] += p_[i][jj] * v_[j];
            }
        }
        __syncthreads();
    }

    // ---- final normalize + write [B,S,E] ----
#pragma unroll
    for (int i = 0; i < 4; i++) {
        float inv = 1.f / lrow[ty * 4 + i];
        int rg = q0 + ty * 4 + i;
        float4 o = make_float4(acc[i][0] * inv, acc[i][1] * inv,
                               acc[i][2] * inv, acc[i][3] * inv);
        *(float4*)&g_attn[((size_t)b * S_LEN + rg) * E_DIM + h * DK_ + tx * 4] = o;
    }
}

// ======================================================================
// Fused: x1 = LN1(x + proj);  f = sum_i cos(x1_i)cos(theta_i)w1_i + b1;
//        out = LN2(x1 + f).  One block (256 thr) per token.
// ======================================================================
__global__ __launch_bounds__(256) void ln_fused(const float* __restrict__ x,
                                                const float* __restrict__ g1,
                                                const float* __restrict__ be1,
                                                const float* __restrict__ g2,
                                                const float* __restrict__ be2,
                                                const float* __restrict__ theta,
                                                const float* __restrict__ w1,
                                                const float* __restrict__ b1s,
                                                float* __restrict__ out)
{
    const int row = blockIdx.x;
    const int tid = threadIdx.x;
    const float* xr = x + (size_t)row * E_DIM;
    const float* pr = g_proj + (size_t)row * E_DIM;

    __shared__ float red[16];
    __shared__ float sx1[8];

    float v[4];
#pragma unroll
    for (int i = 0; i < 4; i++) v[i] = xr[tid + i * 256] + pr[tid + i * 256];

    // reduction 1: sum, sumsq
    float s = 0.f, ss = 0.f;
#pragma unroll
    for (int i = 0; i < 4; i++) { s += v[i]; ss += v[i] * v[i]; }
#pragma unroll
    for (int o = 16; o > 0; o >>= 1) {
        s  += __shfl_xor_sync(0xffffffffu, s, o);
        ss += __shfl_xor_sync(0xffffffffu, ss, o);
    }
    if ((tid & 31) == 0) { red[tid >> 5] = s; red[8 + (tid >> 5)] = ss; }
    __syncthreads();
    s = 0.f; ss = 0.f;
#pragma unroll
    for (int w = 0; w < 8; w++) { s += red[w]; ss += red[8 + w]; }
    float mean = s * (1.f / E_DIM);
    float var  = ss * (1.f / E_DIM) - mean * mean;
    float rs = rsqrtf(var + 1e-5f);

    float x1[4];
#pragma unroll
    for (int i = 0; i < 4; i++) {
        int c = tid + i * 256;
        x1[i] = (v[i] - mean) * rs * g1[c] + be1[c];
    }
    if (tid < 8) sx1[tid] = x1[0];   // global cols 0..7 live in threads 0..7 (i=0)
    __syncthreads();

    float f = b1s[0];
#pragma unroll
    for (int q = 0; q < 8; q++) f += cosf(sx1[q]) * cosf(theta[q]) * w1[q];

    // reduction 2 on y = x1 + f
    float y[4];
    s = 0.f; ss = 0.f;
#pragma unroll
    for (int i = 0; i < 4; i++) { y[i] = x1[i] + f; s += y[i]; ss += y[i] * y[i]; }
#pragma unroll
    for (int o = 16; o > 0; o >>= 1) {
        s  += __shfl_xor_sync(0xffffffffu, s, o);
        ss += __shfl_xor_sync(0xffffffffu, ss, o);
    }
    if ((tid & 31) == 0) { red[tid >> 5] = s; red[8 + (tid >> 5)] = ss; }
    __syncthreads();
    s = 0.f; ss = 0.f;
#pragma unroll
    for (int w = 0; w < 8; w++) { s += red[w]; ss += red[8 + w]; }
    float mean2 = s * (1.f / E_DIM);
    float var2  = ss * (1.f / E_DIM) - mean2 * mean2;
    float rs2 = rsqrtf(var2 + 1e-5f);
#pragma unroll
    for (int i = 0; i < 4; i++) {
        int c = tid + i * 256;
        out[(size_t)row * E_DIM + c] = (y[i] - mean2) * rs2 * g2[c] + be2[c];
    }
}

// ======================================================================
extern "C" void kernel_launch(void* const* d_in, const int* in_sizes, int n_in,
                              void* d_out, int out_size)
{
    const float* x      = (const float*)d_in[0];
    const float* w_qkv  = (const float*)d_in[1];
    const float* w_comb = (const float*)d_in[2];
    const float* b_comb = (const float*)d_in[3];
    const float* gamma1 = (const float*)d_in[4];
    const float* beta1  = (const float*)d_in[5];
    const float* gamma2 = (const float*)d_in[6];
    const float* beta2  = (const float*)d_in[7];
    const float* theta  = (const float*)d_in[8];
    const float* w1     = (const float*)d_in[9];
    const float* b1     = (const float*)d_in[10];

    cudaFuncSetAttribute(flash_attn, cudaFuncAttributeMaxDynamicSharedMemorySize,
                         FLASH_SMEM_BYTES);

    gemm_qkv<<<dim3(N_QKV / 128, M_TOK / 128), 256>>>(x, w_qkv);
    flash_attn<<<dim3(S_LEN / 64, H_NUM, B_SZ), 256, FLASH_SMEM_BYTES>>>();
    gemm_out<<<dim3(E_DIM / 128, M_TOK / 128), 256>>>(w_comb, b_comb);
    ln_fused<<<M_TOK, 256>>>(x, gamma1, beta1, gamma2, beta2, theta, w1, b1,
                             (float*)d_out);
}

// round 4
// speedup vs baseline: 1.4726x; 1.4726x over previous
#include <cuda_runtime.h>
#include <cstdint>
#include <math.h>

// ---------------- problem constants ----------------
#define E_DIM  1024
#define H_NUM  16
#define DK_    64
#define B_SZ   2
#define S_LEN  2048
#define M_TOK  (B_SZ * S_LEN)       // 4096 tokens
#define N_QKV  (3 * E_DIM)          // 3072
#define K_DIM  1024

// ---------------- device scratch (alloc-free) ----------------
__device__ float g_q[B_SZ * H_NUM * S_LEN * DK_];     // [B,H,S,dk]
__device__ float g_k[B_SZ * H_NUM * S_LEN * DK_];
__device__ float g_v[B_SZ * H_NUM * S_LEN * DK_];
__device__ float g_attn[M_TOK * E_DIM];               // [B,S,E]
__device__ float g_proj[M_TOK * E_DIM];               // [B,S,E]

// ======================================================================
// tf32 mma.sync GEMM: C[M,N] = A[M,K] @ W[N,K]^T
// CTA tile 128x128, BK=32, double-buffered smem, 8 warps (2m x 4n),
// warp tile 64x32 -> 4x4 grid of m16n8k8 tf32 MMAs.
// MODE 0: A = x,      scatter into g_q/g_k/g_v ([B,H,S,dk])
// MODE 1: A = g_attn, +bias, write g_proj ([B,S,E])
// ======================================================================
#define BM 128
#define BN 128
#define BK 32
#define LDA 36                         // padded row (floats): bank = (4r+c)%32
#define STAGE_FLOATS (BM * LDA)        // 4608
#define GEMM_SMEM_BYTES (4 * STAGE_FLOATS * 4)   // A[2] + B[2] = 73728 B

__device__ __forceinline__ uint32_t f2tf32(float f) {
    uint32_t r;
    asm("cvt.rna.tf32.f32 %0, %1;" : "=r"(r) : "f"(f));
    return r;
}

__device__ __forceinline__ void mma_tf32(float c[4], const uint32_t a[4],
                                         const uint32_t b[2]) {
    asm volatile(
        "mma.sync.aligned.m16n8k8.row.col.f32.tf32.tf32.f32 "
        "{%0,%1,%2,%3}, {%4,%5,%6,%7}, {%8,%9}, {%0,%1,%2,%3};"
        : "+f"(c[0]), "+f"(c[1]), "+f"(c[2]), "+f"(c[3])
        : "r"(a[0]), "r"(a[1]), "r"(a[2]), "r"(a[3]), "r"(b[0]), "r"(b[1]));
}

template <int MODE>
__global__ __launch_bounds__(256) void gemm_mma(const float* __restrict__ Ain,
                                                const float* __restrict__ W,
                                                const float* __restrict__ bias)
{
    extern __shared__ uint32_t sh[];
    uint32_t* As = sh;                         // [2][STAGE_FLOATS]
    uint32_t* Bs = sh + 2 * STAGE_FLOATS;      // [2][STAGE_FLOATS]

    const float* __restrict__ A = (MODE == 1) ? (const float*)g_attn : Ain;

    const int tid = threadIdx.x;
    const int wid = tid >> 5;
    const int lane = tid & 31;
    const int warp_m = wid & 1;                // 0..1 (64 rows each)
    const int warp_n = wid >> 1;               // 0..3 (32 cols each)
    const int m0 = blockIdx.y * BM;
    const int n0 = blockIdx.x * BN;

    const int ld_row = tid >> 3;               // 0..31 base rows (x4 iters -> 128)
    const int ld_c4  = tid & 7;                // float4 index within 32-float row

    float acc[4][4][4];
#pragma unroll
    for (int mt = 0; mt < 4; mt++)
#pragma unroll
        for (int nt = 0; nt < 4; nt++)
#pragma unroll
            for (int e = 0; e < 4; e++) acc[mt][nt][e] = 0.f;

    // ---- helper lambda-free stage fill (k0 = chunk start) ----
    // prologue: stage 0
    {
#pragma unroll
        for (int it = 0; it < 4; it++) {
            int r = ld_row + it * 32;
            float4 av = *(const float4*)&A[(size_t)(m0 + r) * K_DIM + ld_c4 * 4];
            float4 wv = *(const float4*)&W[(size_t)(n0 + r) * K_DIM + ld_c4 * 4];
            uint32_t* ap = &As[r * LDA + ld_c4 * 4];
            ap[0] = f2tf32(av.x); ap[1] = f2tf32(av.y);
            ap[2] = f2tf32(av.z); ap[3] = f2tf32(av.w);
            uint32_t* bp = &Bs[r * LDA + ld_c4 * 4];
            bp[0] = f2tf32(wv.x); bp[1] = f2tf32(wv.y);
            bp[2] = f2tf32(wv.z); bp[3] = f2tf32(wv.w);
        }
    }
    __syncthreads();

    const int NK = K_DIM / BK;                 // 32
    for (int t = 0; t < NK; t++) {
        const int s = t & 1;
        const uint32_t* Asl = As + s * STAGE_FLOATS;
        const uint32_t* Bsl = Bs + s * STAGE_FLOATS;

        // prefetch next chunk into registers
        float4 pav[4], pwv[4];
        if (t + 1 < NK) {
            const int k0 = (t + 1) * BK;
#pragma unroll
            for (int it = 0; it < 4; it++) {
                int r = ld_row + it * 32;
                pav[it] = *(const float4*)&A[(size_t)(m0 + r) * K_DIM + k0 + ld_c4 * 4];
                pwv[it] = *(const float4*)&W[(size_t)(n0 + r) * K_DIM + k0 + ld_c4 * 4];
            }
        }

        // compute: 4 k-steps of 8
#pragma unroll
        for (int ks = 0; ks < 4; ks++) {
            const int k0 = ks * 8;
            uint32_t afr[4][4];
#pragma unroll
            for (int mt = 0; mt < 4; mt++) {
                const int row = warp_m * 64 + mt * 16 + (lane >> 2);
                const int col = k0 + (lane & 3);
                afr[mt][0] = Asl[row * LDA + col];
                afr[mt][1] = Asl[(row + 8) * LDA + col];
                afr[mt][2] = Asl[row * LDA + col + 4];
                afr[mt][3] = Asl[(row + 8) * LDA + col + 4];
            }
            uint32_t bfr[4][2];
#pragma unroll
            for (int nt = 0; nt < 4; nt++) {
                const int nrow = warp_n * 32 + nt * 8 + (lane >> 2);
                const int col = k0 + (lane & 3);
                bfr[nt][0] = Bsl[nrow * LDA + col];
                bfr[nt][1] = Bsl[nrow * LDA + col + 4];
            }
#pragma unroll
            for (int mt = 0; mt < 4; mt++)
#pragma unroll
                for (int nt = 0; nt < 4; nt++)
                    mma_tf32(acc[mt][nt], afr[mt], bfr[nt]);
        }
        __syncthreads();

        // store prefetched chunk to the other stage
        if (t + 1 < NK) {
            uint32_t* Asn = As + (s ^ 1) * STAGE_FLOATS;
            uint32_t* Bsn = Bs + (s ^ 1) * STAGE_FLOATS;
#pragma unroll
            for (int it = 0; it < 4; it++) {
                int r = ld_row + it * 32;
                uint32_t* ap = &Asn[r * LDA + ld_c4 * 4];
                ap[0] = f2tf32(pav[it].x); ap[1] = f2tf32(pav[it].y);
                ap[2] = f2tf32(pav[it].z); ap[3] = f2tf32(pav[it].w);
                uint32_t* bp = &Bsn[r * LDA + ld_c4 * 4];
                bp[0] = f2tf32(pwv[it].x); bp[1] = f2tf32(pwv[it].y);
                bp[2] = f2tf32(pwv[it].z); bp[3] = f2tf32(pwv[it].w);
            }
            __syncthreads();
        }
    }

    // ---- epilogue ----
#pragma unroll
    for (int mt = 0; mt < 4; mt++) {
        const int m_lo = m0 + warp_m * 64 + mt * 16 + (lane >> 2);
        const int m_hi = m_lo + 8;
#pragma unroll
        for (int nt = 0; nt < 4; nt++) {
            const int n = n0 + warp_n * 32 + nt * 8 + 2 * (lane & 3);
            if (MODE == 0) {
                const int which = n >> 10;
                const int h = (n >> 6) & 15;
                const int d0 = n & 63;
                float* dst = (which == 0) ? g_q : (which == 1) ? g_k : g_v;
                {
                    const int b = m_lo >> 11, sq = m_lo & 2047;
                    size_t base = (((size_t)(b * H_NUM + h)) * S_LEN + sq) * DK_ + d0;
                    *(float2*)&dst[base] = make_float2(acc[mt][nt][0], acc[mt][nt][1]);
                }
                {
                    const int b = m_hi >> 11, sq = m_hi & 2047;
                    size_t base = (((size_t)(b * H_NUM + h)) * S_LEN + sq) * DK_ + d0;
                    *(float2*)&dst[base] = make_float2(acc[mt][nt][2], acc[mt][nt][3]);
                }
            } else {
                const float b0 = bias[n], b1 = bias[n + 1];
                *(float2*)&g_proj[(size_t)m_lo * E_DIM + n] =
                    make_float2(acc[mt][nt][0] + b0, acc[mt][nt][1] + b1);
                *(float2*)&g_proj[(size_t)m_hi * E_DIM + n] =
                    make_float2(acc[mt][nt][2] + b0, acc[mt][nt][3] + b1);
            }
        }
    }
}

// ======================================================================
// Flash attention (fp32) — unchanged (passing).
// ======================================================================
#define QS_LD 68
#define KS_LD 65
#define VS_LD 68
#define PS_LD 68
#define FLASH_SMEM_FLOATS (64*QS_LD + 64*KS_LD + 64*VS_LD + 64*PS_LD + 128)
#define FLASH_SMEM_BYTES  (FLASH_SMEM_FLOATS * 4)

__global__ __launch_bounds__(256) void flash_attn()
{
    extern __shared__ float sm[];
    float* Qs   = sm;
    float* Ks   = Qs + 64 * QS_LD;
    float* Vs   = Ks + 64 * KS_LD;
    float* Ps   = Vs + 64 * VS_LD;
    float* mrow = Ps + 64 * PS_LD;
    float* lrow = mrow + 64;

    const int tid = threadIdx.x;
    const int tx = tid & 15, ty = tid >> 4;
    const int b = blockIdx.z, h = blockIdx.y;
    const int q0 = blockIdx.x * 64;
    const size_t hoff = ((size_t)(b * H_NUM + h)) * S_LEN * DK_;

#pragma unroll
    for (int it = 0; it < 4; it++) {
        int idx = tid + it * 256;
        int r = idx >> 4, c = (idx & 15) << 2;
        float4 v = *(const float4*)&g_q[hoff + (size_t)(q0 + r) * DK_ + c];
        v.x *= 0.125f; v.y *= 0.125f; v.z *= 0.125f; v.w *= 0.125f;
        *(float4*)&Qs[r * QS_LD + c] = v;
    }
    if (tid < 64) { mrow[tid] = -1e30f; lrow[tid] = 0.f; }

    float acc[4][4];
#pragma unroll
    for (int i = 0; i < 4; i++)
#pragma unroll
        for (int j = 0; j < 4; j++) acc[i][j] = 0.f;
    __syncthreads();

    for (int kt = 0; kt < S_LEN / 64; kt++) {
        const int k0 = kt * 64;
#pragma unroll
        for (int it = 0; it < 4; it++) {
            int idx = tid + it * 256;
            int r = idx >> 4, c = (idx & 15) << 2;
            float4 kv = *(const float4*)&g_k[hoff + (size_t)(k0 + r) * DK_ + c];
            Ks[r * KS_LD + c + 0] = kv.x; Ks[r * KS_LD + c + 1] = kv.y;
            Ks[r * KS_LD + c + 2] = kv.z; Ks[r * KS_LD + c + 3] = kv.w;
            float4 vv = *(const float4*)&g_v[hoff + (size_t)(k0 + r) * DK_ + c];
            *(float4*)&Vs[r * VS_LD + c] = vv;
        }
        __syncthreads();

        float s[4][4];
#pragma unroll
        for (int i = 0; i < 4; i++)
#pragma unroll
            for (int j = 0; j < 4; j++) s[i][j] = 0.f;

        for (int d0 = 0; d0 < DK_; d0 += 4) {
            float a_[4][4];
#pragma unroll
            for (int i = 0; i < 4; i++) {
                float4 t = *(const float4*)&Qs[(ty * 4 + i) * QS_LD + d0];
                a_[i][0] = t.x; a_[i][1] = t.y; a_[i][2] = t.z; a_[i][3] = t.w;
            }
#pragma unroll
            for (int dd = 0; dd < 4; dd++) {
                float bk[4];
#pragma unroll
                for (int j = 0; j < 4; j++) bk[j] = Ks[(tx * 4 + j) * KS_LD + d0 + dd];
#pragma unroll
                for (int i = 0; i < 4; i++)
#pragma unroll
                    for (int j = 0; j < 4; j++) s[i][j] += a_[i][dd] * bk[j];
            }
        }

#pragma unroll
        for (int i = 0; i < 4; i++) {
            const int row = ty * 4 + i;
            float rm = fmaxf(fmaxf(s[i][0], s[i][1]), fmaxf(s[i][2], s[i][3]));
            rm = fmaxf(rm, __shfl_xor_sync(0xffffffffu, rm, 1));
            rm = fmaxf(rm, __shfl_xor_sync(0xffffffffu, rm, 2));
            rm = fmaxf(rm, __shfl_xor_sync(0xffffffffu, rm, 4));
            rm = fmaxf(rm, __shfl_xor_sync(0xffffffffu, rm, 8));
            float mo = mrow[row];
            float mn = fmaxf(mo, rm);
            float sum = 0.f;
#pragma unroll
            for (int j = 0; j < 4; j++) {
                float p = __expf(s[i][j] - mn);
                s[i][j] = p;
                sum += p;
            }
            sum += __shfl_xor_sync(0xffffffffu, sum, 1);
            sum += __shfl_xor_sync(0xffffffffu, sum, 2);
            sum += __shfl_xor_sync(0xffffffffu, sum, 4);
            sum += __shfl_xor_sync(0xffffffffu, sum, 8);
            float sc = __expf(mo - mn);
#pragma unroll
            for (int j = 0; j < 4; j++) acc[i][j] *= sc;
            if (tx == 0) {
                mrow[row] = mn;
                lrow[row] = lrow[row] * sc + sum;
            }
            *(float4*)&Ps[row * PS_LD + tx * 4] =
                make_float4(s[i][0], s[i][1], s[i][2], s[i][3]);
        }
        __syncwarp();

        for (int j0 = 0; j0 < 64; j0 += 4) {
            float p_[4][4];
#pragma unroll
            for (int i = 0; i < 4; i++) {
                float4 t = *(const float4*)&Ps[(ty * 4 + i) * PS_LD + j0];
                p_[i][0] = t.x; p_[i][1] = t.y; p_[i][2] = t.z; p_[i][3] = t.w;
            }
#pragma unroll
            for (int jj = 0; jj < 4; jj++) {
                float4 v4 = *(const float4*)&Vs[(j0 + jj) * VS_LD + tx * 4];
                float v_[4] = {v4.x, v4.y, v4.z, v4.w};
#pragma unroll
                for (int i = 0; i < 4; i++)
#pragma unroll
                    for (int j = 0; j < 4; j++) acc[i][j] += p_[i][jj] * v_[j];
            }
        }
        __syncthreads();
    }

#pragma unroll
    for (int i = 0; i < 4; i++) {
        float inv = 1.f / lrow[ty * 4 + i];
        int rg = q0 + ty * 4 + i;
        float4 o = make_float4(acc[i][0] * inv, acc[i][1] * inv,
                               acc[i][2] * inv, acc[i][3] * inv);
        *(float4*)&g_attn[((size_t)b * S_LEN + rg) * E_DIM + h * DK_ + tx * 4] = o;
    }
}

// ======================================================================
// Fused LN1 + quantum FFN + LN2 — unchanged (passing).
// ======================================================================
__global__ __launch_bounds__(256) void ln_fused(const float* __restrict__ x,
                                                const float* __restrict__ g1,
                                                const float* __restrict__ be1,
                                                const float* __restrict__ g2,
                                                const float* __restrict__ be2,
                                                const float* __restrict__ theta,
                                                const float* __restrict__ w1,
                                                const float* __restrict__ b1s,
                                                float* __restrict__ out)
{
    const int row = blockIdx.x;
    const int tid = threadIdx.x;
    const float* xr = x + (size_t)row * E_DIM;
    const float* pr = g_proj + (size_t)row * E_DIM;

    __shared__ float red[16];
    __shared__ float sx1[8];

    float v[4];
#pragma unroll
    for (int i = 0; i < 4; i++) v[i] = xr[tid + i * 256] + pr[tid + i * 256];

    float s = 0.f, ss = 0.f;
#pragma unroll
    for (int i = 0; i < 4; i++) { s += v[i]; ss += v[i] * v[i]; }
#pragma unroll
    for (int o = 16; o > 0; o >>= 1) {
        s  += __shfl_xor_sync(0xffffffffu, s, o);
        ss += __shfl_xor_sync(0xffffffffu, ss, o);
    }
    if ((tid & 31) == 0) { red[tid >> 5] = s; red[8 + (tid >> 5)] = ss; }
    __syncthreads();
    s = 0.f; ss = 0.f;
#pragma unroll
    for (int w = 0; w < 8; w++) { s += red[w]; ss += red[8 + w]; }
    float mean = s * (1.f / E_DIM);
    float var  = ss * (1.f / E_DIM) - mean * mean;
    float rs = rsqrtf(var + 1e-5f);

    float x1[4];
#pragma unroll
    for (int i = 0; i < 4; i++) {
        int c = tid + i * 256;
        x1[i] = (v[i] - mean) * rs * g1[c] + be1[c];
    }
    if (tid < 8) sx1[tid] = x1[0];
    __syncthreads();

    float f = b1s[0];
#pragma unroll
    for (int q = 0; q < 8; q++) f += cosf(sx1[q]) * cosf(theta[q]) * w1[q];

    float y[4];
    s = 0.f; ss = 0.f;
#pragma unroll
    for (int i = 0; i < 4; i++) { y[i] = x1[i] + f; s += y[i]; ss += y[i] * y[i]; }
#pragma unroll
    for (int o = 16; o > 0; o >>= 1) {
        s  += __shfl_xor_sync(0xffffffffu, s, o);
        ss += __shfl_xor_sync(0xffffffffu, ss, o);
    }
    if ((tid & 31) == 0) { red[tid >> 5] = s; red[8 + (tid >> 5)] = ss; }
    __syncthreads();
    s = 0.f; ss = 0.f;
#pragma unroll
    for (int w = 0; w < 8; w++) { s += red[w]; ss += red[8 + w]; }
    float mean2 = s * (1.f / E_DIM);
    float var2  = ss * (1.f / E_DIM) - mean2 * mean2;
    float rs2 = rsqrtf(var2 + 1e-5f);
#pragma unroll
    for (int i = 0; i < 4; i++) {
        int c = tid + i * 256;
        out[(size_t)row * E_DIM + c] = (y[i] - mean2) * rs2 * g2[c] + be2[c];
    }
}

// ======================================================================
extern "C" void kernel_launch(void* const* d_in, const int* in_sizes, int n_in,
                              void* d_out, int out_size)
{
    const float* x      = (const float*)d_in[0];
    const float* w_qkv  = (const float*)d_in[1];
    const float* w_comb = (const float*)d_in[2];
    const float* b_comb = (const float*)d_in[3];
    const float* gamma1 = (const float*)d_in[4];
    const float* beta1  = (const float*)d_in[5];
    const float* gamma2 = (const float*)d_in[6];
    const float* beta2  = (const float*)d_in[7];
    const float* theta  = (const float*)d_in[8];
    const float* w1     = (const float*)d_in[9];
    const float* b1     = (const float*)d_in[10];

    cudaFuncSetAttribute(gemm_mma<0>, cudaFuncAttributeMaxDynamicSharedMemorySize,
                         GEMM_SMEM_BYTES);
    cudaFuncSetAttribute(gemm_mma<1>, cudaFuncAttributeMaxDynamicSharedMemorySize,
                         GEMM_SMEM_BYTES);
    cudaFuncSetAttribute(flash_attn, cudaFuncAttributeMaxDynamicSharedMemorySize,
                         FLASH_SMEM_BYTES);

    gemm_mma<0><<<dim3(N_QKV / BN, M_TOK / BM), 256, GEMM_SMEM_BYTES>>>(x, w_qkv, nullptr);
    flash_attn<<<dim3(S_LEN / 64, H_NUM, B_SZ), 256, FLASH_SMEM_BYTES>>>();
    gemm_mma<1><<<dim3(E_DIM / BN, M_TOK / BM), 256, GEMM_SMEM_BYTES>>>(nullptr, w_comb, b_comb);
    ln_fused<<<M_TOK, 256>>>(x, gamma1, beta1, gamma2, beta2, theta, w1, b1,
                             (float*)d_out);
}

// round 5
// speedup vs baseline: 2.4943x; 1.6938x over previous
#include <cuda_runtime.h>
#include <cstdint>
#include <math.h>

// ---------------- problem constants ----------------
#define E_DIM  1024
#define H_NUM  16
#define DK_    64
#define B_SZ   2
#define S_LEN  2048
#define M_TOK  (B_SZ * S_LEN)       // 4096 tokens
#define N_QKV  (3 * E_DIM)          // 3072
#define K_DIM  1024

// ---------------- device scratch (alloc-free) ----------------
__device__ float g_q[B_SZ * H_NUM * S_LEN * DK_];     // [B,H,S,dk]
__device__ float g_k[B_SZ * H_NUM * S_LEN * DK_];
__device__ float g_v[B_SZ * H_NUM * S_LEN * DK_];
__device__ float g_attn[M_TOK * E_DIM];               // [B,S,E]
__device__ float g_proj[M_TOK * E_DIM];               // [B,S,E]

__device__ __forceinline__ uint32_t f2tf32(float f) {
    uint32_t r;
    asm("cvt.rna.tf32.f32 %0, %1;" : "=r"(r) : "f"(f));
    return r;
}

__device__ __forceinline__ void mma_tf32(float c[4], const uint32_t a[4],
                                         const uint32_t b0, const uint32_t b1) {
    asm volatile(
        "mma.sync.aligned.m16n8k8.row.col.f32.tf32.tf32.f32 "
        "{%0,%1,%2,%3}, {%4,%5,%6,%7}, {%8,%9}, {%0,%1,%2,%3};"
        : "+f"(c[0]), "+f"(c[1]), "+f"(c[2]), "+f"(c[3])
        : "r"(a[0]), "r"(a[1]), "r"(a[2]), "r"(a[3]), "r"(b0), "r"(b1));
}

// ======================================================================
// tf32 mma.sync GEMM (as round 4, passing): C[M,N] = A[M,K] @ W[N,K]^T
// ======================================================================
#define BM 128
#define BN 128
#define BK 32
#define LDA 36
#define STAGE_FLOATS (BM * LDA)
#define GEMM_SMEM_BYTES (4 * STAGE_FLOATS * 4)

template <int MODE>
__global__ __launch_bounds__(256) void gemm_mma(const float* __restrict__ Ain,
                                                const float* __restrict__ W,
                                                const float* __restrict__ bias)
{
    extern __shared__ uint32_t sh[];
    uint32_t* As = sh;
    uint32_t* Bs = sh + 2 * STAGE_FLOATS;

    const float* __restrict__ A = (MODE == 1) ? (const float*)g_attn : Ain;

    const int tid = threadIdx.x;
    const int wid = tid >> 5;
    const int lane = tid & 31;
    const int warp_m = wid & 1;
    const int warp_n = wid >> 1;
    const int m0 = blockIdx.y * BM;
    const int n0 = blockIdx.x * BN;

    const int ld_row = tid >> 3;
    const int ld_c4  = tid & 7;

    float acc[4][4][4];
#pragma unroll
    for (int mt = 0; mt < 4; mt++)
#pragma unroll
        for (int nt = 0; nt < 4; nt++)
#pragma unroll
            for (int e = 0; e < 4; e++) acc[mt][nt][e] = 0.f;

    {
#pragma unroll
        for (int it = 0; it < 4; it++) {
            int r = ld_row + it * 32;
            float4 av = *(const float4*)&A[(size_t)(m0 + r) * K_DIM + ld_c4 * 4];
            float4 wv = *(const float4*)&W[(size_t)(n0 + r) * K_DIM + ld_c4 * 4];
            uint32_t* ap = &As[r * LDA + ld_c4 * 4];
            ap[0] = f2tf32(av.x); ap[1] = f2tf32(av.y);
            ap[2] = f2tf32(av.z); ap[3] = f2tf32(av.w);
            uint32_t* bp = &Bs[r * LDA + ld_c4 * 4];
            bp[0] = f2tf32(wv.x); bp[1] = f2tf32(wv.y);
            bp[2] = f2tf32(wv.z); bp[3] = f2tf32(wv.w);
        }
    }
    __syncthreads();

    const int NK = K_DIM / BK;
    for (int t = 0; t < NK; t++) {
        const int s = t & 1;
        const uint32_t* Asl = As + s * STAGE_FLOATS;
        const uint32_t* Bsl = Bs + s * STAGE_FLOATS;

        float4 pav[4], pwv[4];
        if (t + 1 < NK) {
            const int k0 = (t + 1) * BK;
#pragma unroll
            for (int it = 0; it < 4; it++) {
                int r = ld_row + it * 32;
                pav[it] = *(const float4*)&A[(size_t)(m0 + r) * K_DIM + k0 + ld_c4 * 4];
                pwv[it] = *(const float4*)&W[(size_t)(n0 + r) * K_DIM + k0 + ld_c4 * 4];
            }
        }

#pragma unroll
        for (int ks = 0; ks < 4; ks++) {
            const int k0 = ks * 8;
            uint32_t afr[4][4];
#pragma unroll
            for (int mt = 0; mt < 4; mt++) {
                const int row = warp_m * 64 + mt * 16 + (lane >> 2);
                const int col = k0 + (lane & 3);
                afr[mt][0] = Asl[row * LDA + col];
                afr[mt][1] = Asl[(row + 8) * LDA + col];
                afr[mt][2] = Asl[row * LDA + col + 4];
                afr[mt][3] = Asl[(row + 8) * LDA + col + 4];
            }
            uint32_t bfr[4][2];
#pragma unroll
            for (int nt = 0; nt < 4; nt++) {
                const int nrow = warp_n * 32 + nt * 8 + (lane >> 2);
                const int col = k0 + (lane & 3);
                bfr[nt][0] = Bsl[nrow * LDA + col];
                bfr[nt][1] = Bsl[nrow * LDA + col + 4];
            }
#pragma unroll
            for (int mt = 0; mt < 4; mt++)
#pragma unroll
                for (int nt = 0; nt < 4; nt++)
                    mma_tf32(acc[mt][nt], afr[mt], bfr[nt][0], bfr[nt][1]);
        }
        __syncthreads();

        if (t + 1 < NK) {
            uint32_t* Asn = As + (s ^ 1) * STAGE_FLOATS;
            uint32_t* Bsn = Bs + (s ^ 1) * STAGE_FLOATS;
#pragma unroll
            for (int it = 0; it < 4; it++) {
                int r = ld_row + it * 32;
                uint32_t* ap = &Asn[r * LDA + ld_c4 * 4];
                ap[0] = f2tf32(pav[it].x); ap[1] = f2tf32(pav[it].y);
                ap[2] = f2tf32(pav[it].z); ap[3] = f2tf32(pav[it].w);
                uint32_t* bp = &Bsn[r * LDA + ld_c4 * 4];
                bp[0] = f2tf32(pwv[it].x); bp[1] = f2tf32(pwv[it].y);
                bp[2] = f2tf32(pwv[it].z); bp[3] = f2tf32(pwv[it].w);
            }
            __syncthreads();
        }
    }

#pragma unroll
    for (int mt = 0; mt < 4; mt++) {
        const int m_lo = m0 + warp_m * 64 + mt * 16 + (lane >> 2);
        const int m_hi = m_lo + 8;
#pragma unroll
        for (int nt = 0; nt < 4; nt++) {
            const int n = n0 + warp_n * 32 + nt * 8 + 2 * (lane & 3);
            if (MODE == 0) {
                const int which = n >> 10;
                const int h = (n >> 6) & 15;
                const int d0 = n & 63;
                float* dst = (which == 0) ? g_q : (which == 1) ? g_k : g_v;
                {
                    const int b = m_lo >> 11, sq = m_lo & 2047;
                    size_t base = (((size_t)(b * H_NUM + h)) * S_LEN + sq) * DK_ + d0;
                    *(float2*)&dst[base] = make_float2(acc[mt][nt][0], acc[mt][nt][1]);
                }
                {
                    const int b = m_hi >> 11, sq = m_hi & 2047;
                    size_t base = (((size_t)(b * H_NUM + h)) * S_LEN + sq) * DK_ + d0;
                    *(float2*)&dst[base] = make_float2(acc[mt][nt][2], acc[mt][nt][3]);
                }
            } else {
                const float b0 = bias[n], b1 = bias[n + 1];
                *(float2*)&g_proj[(size_t)m_lo * E_DIM + n] =
                    make_float2(acc[mt][nt][0] + b0, acc[mt][nt][1] + b1);
                *(float2*)&g_proj[(size_t)m_hi * E_DIM + n] =
                    make_float2(acc[mt][nt][2] + b0, acc[mt][nt][3] + b1);
            }
        }
    }
}

// ======================================================================
// Flash attention on tf32 mma.sync.
// CTA: 256 thr / 8 warps. BQ=128 (16 rows per warp), BKV=64, dk=64.
// Smem (permuted pair layouts, all fragment loads = LDS.64 conflict-free):
//   Kp[kk][key][la]  = {K[key][8kk+la], K[key][8kk+la+4]}         16 KB
//   Vp[kk][d][la]    = {V[8kk+la][d],   V[8kk+la+4][d]}           16 KB
//   PQ region (34816 B): Q staging [128][68] u32, then per-warp
//   P pair buffer Pp[warp][r(8)][68] = {P[r][c], P[r+8][c]}.
// ======================================================================
#define FLASH2_SMEM (16384 + 16384 + 34816)

__global__ __launch_bounds__(256) void flash_mma()
{
    extern __shared__ uint32_t fsm[];
    uint2*    Kp = (uint2*)fsm;             // 2048 uint2
    uint2*    Vp = (uint2*)(fsm + 4096);    // 2048 uint2
    uint32_t* Qs = fsm + 8192;              // 8704 u32 (128 x 68)
    uint2*    Pp = (uint2*)(fsm + 8192);    // aliases Qs; per-warp 544 uint2

    const int tid = threadIdx.x;
    const int wid = tid >> 5;
    const int lane = tid & 31;
    const int mu = lane >> 2;               // 0..7
    const int la = lane & 3;                // 0..3
    const int b = blockIdx.z, h = blockIdx.y;
    const int q0 = blockIdx.x * 128;
    const size_t hoff = ((size_t)(b * H_NUM + h)) * S_LEN * DK_;

    // ---- stage Q (scaled by 1/8, tf32) ----
#pragma unroll
    for (int it = 0; it < 8; it++) {
        int slot = tid + it * 256;
        int row = slot >> 4, c4 = slot & 15;
        float4 v = *(const float4*)&g_q[hoff + (size_t)(q0 + row) * DK_ + c4 * 4];
        uint32_t* qp = &Qs[row * 68 + c4 * 4];
        qp[0] = f2tf32(v.x * 0.125f); qp[1] = f2tf32(v.y * 0.125f);
        qp[2] = f2tf32(v.z * 0.125f); qp[3] = f2tf32(v.w * 0.125f);
    }
    __syncthreads();

    // ---- Q fragments to registers (loop-invariant) ----
    uint32_t qf[8][4];
#pragma unroll
    for (int kk = 0; kk < 8; kk++) {
        const int r0 = wid * 16 + mu;
        qf[kk][0] = Qs[r0 * 68 + kk * 8 + la];
        qf[kk][1] = Qs[(r0 + 8) * 68 + kk * 8 + la];
        qf[kk][2] = Qs[r0 * 68 + kk * 8 + la + 4];
        qf[kk][3] = Qs[(r0 + 8) * 68 + kk * 8 + la + 4];
    }

    float m0 = -1e30f, m1 = -1e30f, l0 = 0.f, l1 = 0.f;
    float acc[8][4];
#pragma unroll
    for (int j = 0; j < 8; j++)
#pragma unroll
        for (int e = 0; e < 4; e++) acc[j][e] = 0.f;

    uint2* Pw = Pp + wid * 544;

    for (int kt = 0; kt < S_LEN / 64; kt++) {
        const int k0 = kt * 64;
        __syncthreads();                    // protect K/V restage (and Qs on kt=0)

        // ---- stage K chunk into pair layout ----
#pragma unroll
        for (int it = 0; it < 2; it++) {
            int item = tid + it * 256;
            int kk = item & 7, key = item >> 3;
            const float* kr = &g_k[hoff + (size_t)(k0 + key) * DK_ + kk * 8];
            float4 a = *(const float4*)kr;
            float4 c = *(const float4*)(kr + 4);
            uint2* dst = &Kp[kk * 256 + key * 4];
            dst[0] = make_uint2(f2tf32(a.x), f2tf32(c.x));
            dst[1] = make_uint2(f2tf32(a.y), f2tf32(c.y));
            dst[2] = make_uint2(f2tf32(a.z), f2tf32(c.z));
            dst[3] = make_uint2(f2tf32(a.w), f2tf32(c.w));
        }
        // ---- stage V chunk into transposed pair layout ----
        {
            int dslot = tid & 7, lam = (tid >> 3) & 3, kk = tid >> 5;
            int ra = kk * 8 + lam, rb = ra + 4, d0 = dslot * 8;
            const float* va = &g_v[hoff + (size_t)(k0 + ra) * DK_ + d0];
            const float* vb = &g_v[hoff + (size_t)(k0 + rb) * DK_ + d0];
            float4 a0 = *(const float4*)va, a1 = *(const float4*)(va + 4);
            float4 b0 = *(const float4*)vb, b1 = *(const float4*)(vb + 4);
            uint2* dst = &Vp[kk * 256 + d0 * 4 + lam];
            dst[0]  = make_uint2(f2tf32(a0.x), f2tf32(b0.x));
            dst[4]  = make_uint2(f2tf32(a0.y), f2tf32(b0.y));
            dst[8]  = make_uint2(f2tf32(a0.z), f2tf32(b0.z));
            dst[12] = make_uint2(f2tf32(a0.w), f2tf32(b0.w));
            dst[16] = make_uint2(f2tf32(a1.x), f2tf32(b1.x));
            dst[20] = make_uint2(f2tf32(a1.y), f2tf32(b1.y));
            dst[24] = make_uint2(f2tf32(a1.z), f2tf32(b1.z));
            dst[28] = make_uint2(f2tf32(a1.w), f2tf32(b1.w));
        }
        __syncthreads();

        // ---- S = (Q/8) @ K^T  (16x64 per warp) ----
        float s[8][4];
#pragma unroll
        for (int j = 0; j < 8; j++)
#pragma unroll
            for (int e = 0; e < 4; e++) s[j][e] = 0.f;
#pragma unroll
        for (int kk = 0; kk < 8; kk++) {
#pragma unroll
            for (int j = 0; j < 8; j++) {
                uint2 kb = Kp[kk * 256 + (j * 8 + mu) * 4 + la];
                mma_tf32(s[j], qf[kk], kb.x, kb.y);
            }
        }

        // ---- online softmax (rows r=mu, r+8; quad-replicated stats) ----
        float mx0 = -1e30f, mx1 = -1e30f;
#pragma unroll
        for (int j = 0; j < 8; j++) {
            mx0 = fmaxf(mx0, fmaxf(s[j][0], s[j][1]));
            mx1 = fmaxf(mx1, fmaxf(s[j][2], s[j][3]));
        }
        mx0 = fmaxf(mx0, __shfl_xor_sync(0xffffffffu, mx0, 1));
        mx0 = fmaxf(mx0, __shfl_xor_sync(0xffffffffu, mx0, 2));
        mx1 = fmaxf(mx1, __shfl_xor_sync(0xffffffffu, mx1, 1));
        mx1 = fmaxf(mx1, __shfl_xor_sync(0xffffffffu, mx1, 2));
        const float nm0 = fmaxf(m0, mx0), nm1 = fmaxf(m1, mx1);
        float sum0 = 0.f, sum1 = 0.f;
#pragma unroll
        for (int j = 0; j < 8; j++) {
            s[j][0] = __expf(s[j][0] - nm0);
            s[j][1] = __expf(s[j][1] - nm0);
            s[j][2] = __expf(s[j][2] - nm1);
            s[j][3] = __expf(s[j][3] - nm1);
            sum0 += s[j][0] + s[j][1];
            sum1 += s[j][2] + s[j][3];
        }
        sum0 += __shfl_xor_sync(0xffffffffu, sum0, 1);
        sum0 += __shfl_xor_sync(0xffffffffu, sum0, 2);
        sum1 += __shfl_xor_sync(0xffffffffu, sum1, 1);
        sum1 += __shfl_xor_sync(0xffffffffu, sum1, 2);
        const float sc0 = __expf(m0 - nm0), sc1 = __expf(m1 - nm1);
#pragma unroll
        for (int j = 0; j < 8; j++) {
            acc[j][0] *= sc0; acc[j][1] *= sc0;
            acc[j][2] *= sc1; acc[j][3] *= sc1;
        }
        l0 = l0 * sc0 + sum0; l1 = l1 * sc1 + sum1;
        m0 = nm0; m1 = nm1;

        // ---- write P pairs (tf32) to per-warp buffer ----
#pragma unroll
        for (int j = 0; j < 8; j++) {
            const int c = j * 8 + 2 * la;
            uint4 pk = make_uint4(f2tf32(s[j][0]), f2tf32(s[j][2]),
                                  f2tf32(s[j][1]), f2tf32(s[j][3]));
            *(uint4*)&Pw[mu * 68 + c] = pk;
        }
        __syncwarp();

        // ---- O += P @ V ----
#pragma unroll
        for (int kk = 0; kk < 8; kk++) {
            uint2 pa = Pw[mu * 68 + kk * 8 + la];
            uint2 pb = Pw[mu * 68 + kk * 8 + la + 4];
            uint32_t a[4] = {pa.x, pa.y, pb.x, pb.y};
#pragma unroll
            for (int j = 0; j < 8; j++) {
                uint2 vb = Vp[kk * 256 + (j * 8 + mu) * 4 + la];
                mma_tf32(acc[j], a, vb.x, vb.y);
            }
        }
    }

    // ---- epilogue: normalize and write [B,S,E] ----
    const float i0 = 1.f / l0, i1 = 1.f / l1;
    const int row_a = q0 + wid * 16 + mu;
    const int row_b = row_a + 8;
    float* oa = &g_attn[((size_t)b * S_LEN + row_a) * E_DIM + h * DK_];
    float* ob = &g_attn[((size_t)b * S_LEN + row_b) * E_DIM + h * DK_];
#pragma unroll
    for (int j = 0; j < 8; j++) {
        const int c = j * 8 + 2 * la;
        *(float2*)&oa[c] = make_float2(acc[j][0] * i0, acc[j][1] * i0);
        *(float2*)&ob[c] = make_float2(acc[j][2] * i1, acc[j][3] * i1);
    }
}

// ======================================================================
// Fused LN1 + quantum FFN + LN2 — unchanged (passing).
// ======================================================================
__global__ __launch_bounds__(256) void ln_fused(const float* __restrict__ x,
                                                const float* __restrict__ g1,
                                                const float* __restrict__ be1,
                                                const float* __restrict__ g2,
                                                const float* __restrict__ be2,
                                                const float* __restrict__ theta,
                                                const float* __restrict__ w1,
                                                const float* __restrict__ b1s,
                                                float* __restrict__ out)
{
    const int row = blockIdx.x;
    const int tid = threadIdx.x;
    const float* xr = x + (size_t)row * E_DIM;
    const float* pr = g_proj + (size_t)row * E_DIM;

    __shared__ float red[16];
    __shared__ float sx1[8];

    float v[4];
#pragma unroll
    for (int i = 0; i < 4; i++) v[i] = xr[tid + i * 256] + pr[tid + i * 256];

    float s = 0.f, ss = 0.f;
#pragma unroll
    for (int i = 0; i < 4; i++) { s += v[i]; ss += v[i] * v[i]; }
#pragma unroll
    for (int o = 16; o > 0; o >>= 1) {
        s  += __shfl_xor_sync(0xffffffffu, s, o);
        ss += __shfl_xor_sync(0xffffffffu, ss, o);
    }
    if ((tid & 31) == 0) { red[tid >> 5] = s; red[8 + (tid >> 5)] = ss; }
    __syncthreads();
    s = 0.f; ss = 0.f;
#pragma unroll
    for (int w = 0; w < 8; w++) { s += red[w]; ss += red[8 + w]; }
    float mean = s * (1.f / E_DIM);
    float var  = ss * (1.f / E_DIM) - mean * mean;
    float rs = rsqrtf(var + 1e-5f);

    float x1[4];
#pragma unroll
    for (int i = 0; i < 4; i++) {
        int c = tid + i * 256;
        x1[i] = (v[i] - mean) * rs * g1[c] + be1[c];
    }
    if (tid < 8) sx1[tid] = x1[0];
    __syncthreads();

    float f = b1s[0];
#pragma unroll
    for (int q = 0; q < 8; q++) f += cosf(sx1[q]) * cosf(theta[q]) * w1[q];

    float y[4];
    s = 0.f; ss = 0.f;
#pragma unroll
    for (int i = 0; i < 4; i++) { y[i] = x1[i] + f; s += y[i]; ss += y[i] * y[i]; }
#pragma unroll
    for (int o = 16; o > 0; o >>= 1) {
        s  += __shfl_xor_sync(0xffffffffu, s, o);
        ss += __shfl_xor_sync(0xffffffffu, ss, o);
    }
    if ((tid & 31) == 0) { red[tid >> 5] = s; red[8 + (tid >> 5)] = ss; }
    __syncthreads();
    s = 0.f; ss = 0.f;
#pragma unroll
    for (int w = 0; w < 8; w++) { s += red[w]; ss += red[8 + w]; }
    float mean2 = s * (1.f / E_DIM);
    float var2  = ss * (1.f / E_DIM) - mean2 * mean2;
    float rs2 = rsqrtf(var2 + 1e-5f);
#pragma unroll
    for (int i = 0; i < 4; i++) {
        int c = tid + i * 256;
        out[(size_t)row * E_DIM + c] = (y[i] - mean2) * rs2 * g2[c] + be2[c];
    }
}

// ======================================================================
extern "C" void kernel_launch(void* const* d_in, const int* in_sizes, int n_in,
                              void* d_out, int out_size)
{
    const float* x      = (const float*)d_in[0];
    const float* w_qkv  = (const float*)d_in[1];
    const float* w_comb = (const float*)d_in[2];
    const float* b_comb = (const float*)d_in[3];
    const float* gamma1 = (const float*)d_in[4];
    const float* beta1  = (const float*)d_in[5];
    const float* gamma2 = (const float*)d_in[6];
    const float* beta2  = (const float*)d_in[7];
    const float* theta  = (const float*)d_in[8];
    const float* w1     = (const float*)d_in[9];
    const float* b1     = (const float*)d_in[10];

    cudaFuncSetAttribute(gemm_mma<0>, cudaFuncAttributeMaxDynamicSharedMemorySize,
                         GEMM_SMEM_BYTES);
    cudaFuncSetAttribute(gemm_mma<1>, cudaFuncAttributeMaxDynamicSharedMemorySize,
                         GEMM_SMEM_BYTES);
    cudaFuncSetAttribute(flash_mma, cudaFuncAttributeMaxDynamicSharedMemorySize,
                         FLASH2_SMEM);

    gemm_mma<0><<<dim3(N_QKV / BN, M_TOK / BM), 256, GEMM_SMEM_BYTES>>>(x, w_qkv, nullptr);
    flash_mma<<<dim3(S_LEN / 128, H_NUM, B_SZ), 256, FLASH2_SMEM>>>();
    gemm_mma<1><<<dim3(E_DIM / BN, M_TOK / BM), 256, GEMM_SMEM_BYTES>>>(nullptr, w_comb, b_comb);
    ln_fused<<<M_TOK, 256>>>(x, gamma1, beta1, gamma2, beta2, theta, w1, b1,
                             (float*)d_out);
}

// round 7
// speedup vs baseline: 4.4375x; 1.7790x over previous
#include <cuda_runtime.h>
#include <cuda_bf16.h>
#include <cstdint>
#include <math.h>

// ---------------- problem constants ----------------
#define E_DIM  1024
#define H_NUM  16
#define DK_    64
#define B_SZ   2
#define S_LEN  2048
#define M_TOK  (B_SZ * S_LEN)       // 4096 tokens
#define N_QKV  (3 * E_DIM)          // 3072
#define K_DIM  1024

// ---------------- device scratch (alloc-free) ----------------
__device__ __align__(16) __nv_bfloat16 g_qb[B_SZ * H_NUM * S_LEN * DK_];   // [B,H,S,dk] (x0.125)
__device__ __align__(16) __nv_bfloat16 g_kb[B_SZ * H_NUM * S_LEN * DK_];   // [B,H,S,dk]
__device__ __align__(16) __nv_bfloat16 g_vTb[B_SZ * H_NUM * DK_ * S_LEN];  // [B,H,dk,S]
__device__ float g_attn[M_TOK * E_DIM];               // [B,S,E]
__device__ float g_proj[M_TOK * E_DIM];               // [B,S,E]

__device__ __forceinline__ uint32_t f2tf32(float f) {
    uint32_t r;
    asm("cvt.rna.tf32.f32 %0, %1;" : "=r"(r) : "f"(f));
    return r;
}
__device__ __forceinline__ uint32_t packbf(float lo, float hi) {
    uint32_t r;
    asm("cvt.rn.bf16x2.f32 %0, %1, %2;" : "=r"(r) : "f"(hi), "f"(lo));
    return r;
}

__device__ __forceinline__ void mma_tf32(float c[4], const uint32_t a[4],
                                         const uint32_t b0, const uint32_t b1) {
    asm volatile(
        "mma.sync.aligned.m16n8k8.row.col.f32.tf32.tf32.f32 "
        "{%0,%1,%2,%3}, {%4,%5,%6,%7}, {%8,%9}, {%0,%1,%2,%3};"
        : "+f"(c[0]), "+f"(c[1]), "+f"(c[2]), "+f"(c[3])
        : "r"(a[0]), "r"(a[1]), "r"(a[2]), "r"(a[3]), "r"(b0), "r"(b1));
}
__device__ __forceinline__ void mma_bf16(float c[4], const uint32_t a[4],
                                         const uint32_t b0, const uint32_t b1) {
    asm volatile(
        "mma.sync.aligned.m16n8k16.row.col.f32.bf16.bf16.f32 "
        "{%0,%1,%2,%3}, {%4,%5,%6,%7}, {%8,%9}, {%0,%1,%2,%3};"
        : "+f"(c[0]), "+f"(c[1]), "+f"(c[2]), "+f"(c[3])
        : "r"(a[0]), "r"(a[1]), "r"(a[2]), "r"(a[3]), "r"(b0), "r"(b1));
}

// ======================================================================
// tf32 mma.sync GEMM: C[M,N] = A[M,K] @ W[N,K]^T
// MODE 0: A = x, epilogue -> bf16 g_qb (x0.125) / g_kb / g_vTb (transposed)
// MODE 1: A = g_attn, +bias -> fp32 g_proj
// ======================================================================
#define BM 128
#define BN 128
#define BK 32
#define LDA 36
#define STAGE_FLOATS (BM * LDA)
#define GEMM_SMEM_BYTES (4 * STAGE_FLOATS * 4)

template <int MODE>
__global__ __launch_bounds__(256) void gemm_mma(const float* __restrict__ Ain,
                                                const float* __restrict__ W,
                                                const float* __restrict__ bias)
{
    extern __shared__ uint32_t sh[];
    uint32_t* As = sh;
    uint32_t* Bs = sh + 2 * STAGE_FLOATS;

    const float* __restrict__ A = (MODE == 1) ? (const float*)g_attn : Ain;

    const int tid = threadIdx.x;
    const int wid = tid >> 5;
    const int lane = tid & 31;
    const int warp_m = wid & 1;
    const int warp_n = wid >> 1;
    const int m0 = blockIdx.y * BM;
    const int n0 = blockIdx.x * BN;

    const int ld_row = tid >> 3;
    const int ld_c4  = tid & 7;

    float acc[4][4][4];
#pragma unroll
    for (int mt = 0; mt < 4; mt++)
#pragma unroll
        for (int nt = 0; nt < 4; nt++)
#pragma unroll
            for (int e = 0; e < 4; e++) acc[mt][nt][e] = 0.f;

    {
#pragma unroll
        for (int it = 0; it < 4; it++) {
            int r = ld_row + it * 32;
            float4 av = *(const float4*)&A[(size_t)(m0 + r) * K_DIM + ld_c4 * 4];
            float4 wv = *(const float4*)&W[(size_t)(n0 + r) * K_DIM + ld_c4 * 4];
            uint32_t* ap = &As[r * LDA + ld_c4 * 4];
            ap[0] = f2tf32(av.x); ap[1] = f2tf32(av.y);
            ap[2] = f2tf32(av.z); ap[3] = f2tf32(av.w);
            uint32_t* bp = &Bs[r * LDA + ld_c4 * 4];
            bp[0] = f2tf32(wv.x); bp[1] = f2tf32(wv.y);
            bp[2] = f2tf32(wv.z); bp[3] = f2tf32(wv.w);
        }
    }
    __syncthreads();

    const int NK = K_DIM / BK;
    for (int t = 0; t < NK; t++) {
        const int s = t & 1;
        const uint32_t* Asl = As + s * STAGE_FLOATS;
        const uint32_t* Bsl = Bs + s * STAGE_FLOATS;

        float4 pav[4], pwv[4];
        if (t + 1 < NK) {
            const int k0 = (t + 1) * BK;
#pragma unroll
            for (int it = 0; it < 4; it++) {
                int r = ld_row + it * 32;
                pav[it] = *(const float4*)&A[(size_t)(m0 + r) * K_DIM + k0 + ld_c4 * 4];
                pwv[it] = *(const float4*)&W[(size_t)(n0 + r) * K_DIM + k0 + ld_c4 * 4];
            }
        }

#pragma unroll
        for (int ks = 0; ks < 4; ks++) {
            const int k0 = ks * 8;
            uint32_t afr[4][4];
#pragma unroll
            for (int mt = 0; mt < 4; mt++) {
                const int row = warp_m * 64 + mt * 16 + (lane >> 2);
                const int col = k0 + (lane & 3);
                afr[mt][0] = Asl[row * LDA + col];
                afr[mt][1] = Asl[(row + 8) * LDA + col];
                afr[mt][2] = Asl[row * LDA + col + 4];
                afr[mt][3] = Asl[(row + 8) * LDA + col + 4];
            }
            uint32_t bfr[4][2];
#pragma unroll
            for (int nt = 0; nt < 4; nt++) {
                const int nrow = warp_n * 32 + nt * 8 + (lane >> 2);
                const int col = k0 + (lane & 3);
                bfr[nt][0] = Bsl[nrow * LDA + col];
                bfr[nt][1] = Bsl[nrow * LDA + col + 4];
            }
#pragma unroll
            for (int mt = 0; mt < 4; mt++)
#pragma unroll
                for (int nt = 0; nt < 4; nt++)
                    mma_tf32(acc[mt][nt], afr[mt], bfr[nt][0], bfr[nt][1]);
        }
        __syncthreads();

        if (t + 1 < NK) {
            uint32_t* Asn = As + (s ^ 1) * STAGE_FLOATS;
            uint32_t* Bsn = Bs + (s ^ 1) * STAGE_FLOATS;
#pragma unroll
            for (int it = 0; it < 4; it++) {
                int r = ld_row + it * 32;
                uint32_t* ap = &Asn[r * LDA + ld_c4 * 4];
                ap[0] = f2tf32(pav[it].x); ap[1] = f2tf32(pav[it].y);
                ap[2] = f2tf32(pav[it].z); ap[3] = f2tf32(pav[it].w);
                uint32_t* bp = &Bsn[r * LDA + ld_c4 * 4];
                bp[0] = f2tf32(pwv[it].x); bp[1] = f2tf32(pwv[it].y);
                bp[2] = f2tf32(pwv[it].z); bp[3] = f2tf32(pwv[it].w);
            }
            __syncthreads();
        }
    }

#pragma unroll
    for (int mt = 0; mt < 4; mt++) {
        const int m_lo = m0 + warp_m * 64 + mt * 16 + (lane >> 2);
        const int m_hi = m_lo + 8;
#pragma unroll
        for (int nt = 0; nt < 4; nt++) {
            const int n = n0 + warp_n * 32 + nt * 8 + 2 * (lane & 3);
            if (MODE == 0) {
                const int which = n >> 10;
                const int h = (n >> 6) & 15;
                const int d0 = n & 63;
                const int b = m_lo >> 11;
                const int s_lo = m_lo & 2047, s_hi = m_hi & 2047;
                if (which == 0) {
                    size_t base = (((size_t)(b * H_NUM + h)) * S_LEN);
                    *(__nv_bfloat162*)&g_qb[(base + s_lo) * DK_ + d0] =
                        __floats2bfloat162_rn(acc[mt][nt][0] * 0.125f,
                                              acc[mt][nt][1] * 0.125f);
                    *(__nv_bfloat162*)&g_qb[(base + s_hi) * DK_ + d0] =
                        __floats2bfloat162_rn(acc[mt][nt][2] * 0.125f,
                                              acc[mt][nt][3] * 0.125f);
                } else if (which == 1) {
                    size_t base = (((size_t)(b * H_NUM + h)) * S_LEN);
                    *(__nv_bfloat162*)&g_kb[(base + s_lo) * DK_ + d0] =
                        __floats2bfloat162_rn(acc[mt][nt][0], acc[mt][nt][1]);
                    *(__nv_bfloat162*)&g_kb[(base + s_hi) * DK_ + d0] =
                        __floats2bfloat162_rn(acc[mt][nt][2], acc[mt][nt][3]);
                } else {
                    // transposed store: g_vTb[b,h,d,s]
                    size_t base = (((size_t)(b * H_NUM + h)) * DK_ + d0) * S_LEN;
                    g_vTb[base + s_lo]          = __float2bfloat16_rn(acc[mt][nt][0]);
                    g_vTb[base + S_LEN + s_lo]  = __float2bfloat16_rn(acc[mt][nt][1]);
                    g_vTb[base + s_hi]          = __float2bfloat16_rn(acc[mt][nt][2]);
                    g_vTb[base + S_LEN + s_hi]  = __float2bfloat16_rn(acc[mt][nt][3]);
                }
            } else {
                const float b0 = bias[n], b1 = bias[n + 1];
                *(float2*)&g_proj[(size_t)m_lo * E_DIM + n] =
                    make_float2(acc[mt][nt][0] + b0, acc[mt][nt][1] + b1);
                *(float2*)&g_proj[(size_t)m_hi * E_DIM + n] =
                    make_float2(acc[mt][nt][2] + b0, acc[mt][nt][3] + b1);
            }
        }
    }
}

// ======================================================================
// Flash attention, bf16 m16n8k16 mma, register-resident P.
// CTA: 256 thr / 8 warps. BQ=128 (16 rows/warp), BKV=64, dk=64.
// Double-buffered K/V staging (one __syncthreads per chunk).
// Smem (uint2 units):
//   Kb[st][kk(stride 257)][key][la] : {Kpair(dk 16kk+2la), Kpair(16kk+8+2la)}
//   Vp[st][kk(stride 257)][d][la]   : {Vpair(keys 16kk+2la), Vpair(16kk+8+2la)}
//   Qp[row(stride 20)][kk][la]      : {Qpair(16kk+2la), Qpair(16kk+8+2la)}
// ======================================================================
#define FKB 1028                       // 4 kk-slabs * 257
#define FLASH_U2 (4 * FKB + 128 * 20)  // 6672 uint2
#define FLASH_SMEM_BYTES (FLASH_U2 * 8)

__global__ __launch_bounds__(256, 2) void flash_bf16()
{
    extern __shared__ uint2 fsm[];
    uint2* Qp = fsm + 4 * FKB;

    const int tid = threadIdx.x;
    const int wid = tid >> 5;
    const int lane = tid & 31;
    const int mu = lane >> 2;
    const int la = lane & 3;
    const int b = blockIdx.z, h = blockIdx.y;
    const int q0 = blockIdx.x * 128;
    const size_t hoff = ((size_t)(b * H_NUM + h)) * S_LEN * DK_;

    // ---- per-thread staging addresses ----
    const int kkk = tid & 3, kkey = tid >> 2;      // K: kk slab, key row
    const __nv_bfloat16* ksrc = g_kb + hoff + (size_t)kkey * DK_ + kkk * 16;
    const int vkk = tid & 3, vd = tid >> 2;        // V: kk slab, d row of vT
    const __nv_bfloat16* vsrc = g_vTb + hoff + (size_t)vd * S_LEN + vkk * 16;
    const int kdst_i = kkk * 257 + kkey * 4;
    const int vdst_i = vkk * 257 + vd * 4;

    // ---- stage Q ----
#pragma unroll
    for (int it = 0; it < 2; it++) {
        int item = tid + it * 256;
        int row = item >> 2, kk = item & 3;
        const __nv_bfloat16* qs = g_qb + hoff + (size_t)(q0 + row) * DK_ + kk * 16;
        uint4 u0 = *(const uint4*)qs;
        uint4 u1 = *(const uint4*)(qs + 8);
        uint2* dst = Qp + row * 20 + kk * 4;
        dst[0] = make_uint2(u0.x, u1.x);
        dst[1] = make_uint2(u0.y, u1.y);
        dst[2] = make_uint2(u0.z, u1.z);
        dst[3] = make_uint2(u0.w, u1.w);
    }
    // ---- stage K/V chunk 0 ----
    {
        uint4 k0a = *(const uint4*)ksrc;
        uint4 k0b = *(const uint4*)(ksrc + 8);
        uint4 v0a = *(const uint4*)vsrc;
        uint4 v0b = *(const uint4*)(vsrc + 8);
        uint2* kd = fsm + kdst_i;
        kd[0] = make_uint2(k0a.x, k0b.x); kd[1] = make_uint2(k0a.y, k0b.y);
        kd[2] = make_uint2(k0a.z, k0b.z); kd[3] = make_uint2(k0a.w, k0b.w);
        uint2* vdp = fsm + 2 * FKB + vdst_i;
        vdp[0] = make_uint2(v0a.x, v0b.x); vdp[1] = make_uint2(v0a.y, v0b.y);
        vdp[2] = make_uint2(v0a.z, v0b.z); vdp[3] = make_uint2(v0a.w, v0b.w);
    }
    __syncthreads();

    // ---- Q fragments (loop-invariant) ----
    uint32_t qf[4][4];
    {
        const int r0 = wid * 16 + mu;
#pragma unroll
        for (int kk = 0; kk < 4; kk++) {
            uint2 qa = Qp[r0 * 20 + kk * 4 + la];
            uint2 qb = Qp[(r0 + 8) * 20 + kk * 4 + la];
            qf[kk][0] = qa.x; qf[kk][1] = qb.x;
            qf[kk][2] = qa.y; qf[kk][3] = qb.y;
        }
    }

    float m0 = -1e30f, m1 = -1e30f, l0 = 0.f, l1 = 0.f;
    float acc[8][4];
#pragma unroll
    for (int j = 0; j < 8; j++)
#pragma unroll
        for (int e = 0; e < 4; e++) acc[j][e] = 0.f;

    const int NCH = S_LEN / 64;                    // 32
    for (int kt = 0; kt < NCH; kt++) {
        const uint2* Kc = fsm + (kt & 1) * FKB;
        const uint2* Vc = fsm + 2 * FKB + (kt & 1) * FKB;

        // prefetch next chunk (LDG issued before compute)
        uint4 ku0, ku1, vu0, vu1;
        const bool more = (kt + 1 < NCH);
        if (more) {
            const __nv_bfloat16* ks = ksrc + (size_t)(kt + 1) * 64 * DK_;
            const __nv_bfloat16* vs = vsrc + (size_t)(kt + 1) * 64;
            ku0 = *(const uint4*)ks; ku1 = *(const uint4*)(ks + 8);
            vu0 = *(const uint4*)vs; vu1 = *(const uint4*)(vs + 8);
        }

        // ---- S = Q @ K^T ----
        float s[8][4];
#pragma unroll
        for (int j = 0; j < 8; j++)
#pragma unroll
            for (int e = 0; e < 4; e++) s[j][e] = 0.f;
#pragma unroll
        for (int kk = 0; kk < 4; kk++) {
#pragma unroll
            for (int j = 0; j < 8; j++) {
                uint2 kb = Kc[kk * 257 + (j * 8 + mu) * 4 + la];
                mma_bf16(s[j], qf[kk], kb.x, kb.y);
            }
        }

        // ---- online softmax ----
        float mx0 = -1e30f, mx1 = -1e30f;
#pragma unroll
        for (int j = 0; j < 8; j++) {
            mx0 = fmaxf(mx0, fmaxf(s[j][0], s[j][1]));
            mx1 = fmaxf(mx1, fmaxf(s[j][2], s[j][3]));
        }
        mx0 = fmaxf(mx0, __shfl_xor_sync(0xffffffffu, mx0, 1));
        mx0 = fmaxf(mx0, __shfl_xor_sync(0xffffffffu, mx0, 2));
        mx1 = fmaxf(mx1, __shfl_xor_sync(0xffffffffu, mx1, 1));
        mx1 = fmaxf(mx1, __shfl_xor_sync(0xffffffffu, mx1, 2));
        const float nm0 = fmaxf(m0, mx0), nm1 = fmaxf(m1, mx1);
        float sum0 = 0.f, sum1 = 0.f;
#pragma unroll
        for (int j = 0; j < 8; j++) {
            s[j][0] = __expf(s[j][0] - nm0);
            s[j][1] = __expf(s[j][1] - nm0);
            s[j][2] = __expf(s[j][2] - nm1);
            s[j][3] = __expf(s[j][3] - nm1);
            sum0 += s[j][0] + s[j][1];
            sum1 += s[j][2] + s[j][3];
        }
        sum0 += __shfl_xor_sync(0xffffffffu, sum0, 1);
        sum0 += __shfl_xor_sync(0xffffffffu, sum0, 2);
        sum1 += __shfl_xor_sync(0xffffffffu, sum1, 1);
        sum1 += __shfl_xor_sync(0xffffffffu, sum1, 2);
        const float sc0 = __expf(m0 - nm0), sc1 = __expf(m1 - nm1);
#pragma unroll
        for (int j = 0; j < 8; j++) {
            acc[j][0] *= sc0; acc[j][1] *= sc0;
            acc[j][2] *= sc1; acc[j][3] *= sc1;
        }
        l0 = l0 * sc0 + sum0; l1 = l1 * sc1 + sum1;
        m0 = nm0; m1 = nm1;

        // ---- pack P into A-fragments (register-resident, no smem) ----
        uint32_t pf[4][4];
#pragma unroll
        for (int kk = 0; kk < 4; kk++) {
            pf[kk][0] = packbf(s[2 * kk][0],     s[2 * kk][1]);
            pf[kk][1] = packbf(s[2 * kk][2],     s[2 * kk][3]);
            pf[kk][2] = packbf(s[2 * kk + 1][0], s[2 * kk + 1][1]);
            pf[kk][3] = packbf(s[2 * kk + 1][2], s[2 * kk + 1][3]);
        }

        // ---- O += P @ V ----
#pragma unroll
        for (int kk = 0; kk < 4; kk++) {
#pragma unroll
            for (int j = 0; j < 8; j++) {
                uint2 vb = Vc[kk * 257 + (j * 8 + mu) * 4 + la];
                mma_bf16(acc[j], pf[kk], vb.x, vb.y);
            }
        }

        // ---- stage next chunk into the other buffer ----
        if (more) {
            uint2* kd = fsm + ((kt + 1) & 1) * FKB + kdst_i;
            kd[0] = make_uint2(ku0.x, ku1.x); kd[1] = make_uint2(ku0.y, ku1.y);
            kd[2] = make_uint2(ku0.z, ku1.z); kd[3] = make_uint2(ku0.w, ku1.w);
            uint2* vdp = fsm + 2 * FKB + ((kt + 1) & 1) * FKB + vdst_i;
            vdp[0] = make_uint2(vu0.x, vu1.x); vdp[1] = make_uint2(vu0.y, vu1.y);
            vdp[2] = make_uint2(vu0.z, vu1.z); vdp[3] = make_uint2(vu0.w, vu1.w);
        }
        __syncthreads();
    }

    // ---- epilogue: normalize, write [B,S,E] fp32 ----
    const float i0 = 1.f / l0, i1 = 1.f / l1;
    const int row_a = q0 + wid * 16 + mu;
    const int row_b = row_a + 8;
    float* oa = &g_attn[((size_t)b * S_LEN + row_a) * E_DIM + h * DK_];
    float* ob = &g_attn[((size_t)b * S_LEN + row_b) * E_DIM + h * DK_];
#pragma unroll
    for (int j = 0; j < 8; j++) {
        const int c = j * 8 + 2 * la;
        *(float2*)&oa[c] = make_float2(acc[j][0] * i0, acc[j][1] * i0);
        *(float2*)&ob[c] = make_float2(acc[j][2] * i1, acc[j][3] * i1);
    }
}

// ======================================================================
// Fused LN1 + quantum FFN + LN2 — unchanged (passing).
// ======================================================================
__global__ __launch_bounds__(256) void ln_fused(const float* __restrict__ x,
                                                const float* __restrict__ g1,
                                                const float* __restrict__ be1,
                                                const float* __restrict__ g2,
                                                const float* __restrict__ be2,
                                                const float* __restrict__ theta,
                                                const float* __restrict__ w1,
                                                const float* __restrict__ b1s,
                                                float* __restrict__ out)
{
    const int row = blockIdx.x;
    const int tid = threadIdx.x;
    const float* xr = x + (size_t)row * E_DIM;
    const float* pr = g_proj + (size_t)row * E_DIM;

    __shared__ float red[16];
    __shared__ float sx1[8];

    float v[4];
#pragma unroll
    for (int i = 0; i < 4; i++) v[i] = xr[tid + i * 256] + pr[tid + i * 256];

    float s = 0.f, ss = 0.f;
#pragma unroll
    for (int i = 0; i < 4; i++) { s += v[i]; ss += v[i] * v[i]; }
#pragma unroll
    for (int o = 16; o > 0; o >>= 1) {
        s  += __shfl_xor_sync(0xffffffffu, s, o);
        ss += __shfl_xor_sync(0xffffffffu, ss, o);
    }
    if ((tid & 31) == 0) { red[tid >> 5] = s; red[8 + (tid >> 5)] = ss; }
    __syncthreads();
    s = 0.f; ss = 0.f;
#pragma unroll
    for (int w = 0; w < 8; w++) { s += red[w]; ss += red[8 + w]; }
    float mean = s * (1.f / E_DIM);
    float var  = ss * (1.f / E_DIM) - mean * mean;
    float rs = rsqrtf(var + 1e-5f);

    float x1[4];
#pragma unroll
    for (int i = 0; i < 4; i++) {
        int c = tid + i * 256;
        x1[i] = (v[i] - mean) * rs * g1[c] + be1[c];
    }
    if (tid < 8) sx1[tid] = x1[0];
    __syncthreads();

    float f = b1s[0];
#pragma unroll
    for (int q = 0; q < 8; q++) f += cosf(sx1[q]) * cosf(theta[q]) * w1[q];

    float y[4];
    s = 0.f; ss = 0.f;
#pragma unroll
    for (int i = 0; i < 4; i++) { y[i] = x1[i] + f; s += y[i]; ss += y[i] * y[i]; }
#pragma unroll
    for (int o = 16; o > 0; o >>= 1) {
        s  += __shfl_xor_sync(0xffffffffu, s, o);
        ss += __shfl_xor_sync(0xffffffffu, ss, o);
    }
    if ((tid & 31) == 0) { red[tid >> 5] = s; red[8 + (tid >> 5)] = ss; }
    __syncthreads();
    s = 0.f; ss = 0.f;
#pragma unroll
    for (int w = 0; w < 8; w++) { s += red[w]; ss += red[8 + w]; }
    float mean2 = s * (1.f / E_DIM);
    float var2  = ss * (1.f / E_DIM) - mean2 * mean2;
    float rs2 = rsqrtf(var2 + 1e-5f);
#pragma unroll
    for (int i = 0; i < 4; i++) {
        int c = tid + i * 256;
        out[(size_t)row * E_DIM + c] = (y[i] - mean2) * rs2 * g2[c] + be2[c];
    }
}

// ======================================================================
extern "C" void kernel_launch(void* const* d_in, const int* in_sizes, int n_in,
                              void* d_out, int out_size)
{
    const float* x      = (const float*)d_in[0];
    const float* w_qkv  = (const float*)d_in[1];
    const float* w_comb = (const float*)d_in[2];
    const float* b_comb = (const float*)d_in[3];
    const float* gamma1 = (const float*)d_in[4];
    const float* beta1  = (const float*)d_in[5];
    const float* gamma2 = (const float*)d_in[6];
    const float* beta2  = (const float*)d_in[7];
    const float* theta  = (const float*)d_in[8];
    const float* w1     = (const float*)d_in[9];
    const float* b1     = (const float*)d_in[10];

    cudaFuncSetAttribute(gemm_mma<0>, cudaFuncAttributeMaxDynamicSharedMemorySize,
                         GEMM_SMEM_BYTES);
    cudaFuncSetAttribute(gemm_mma<1>, cudaFuncAttributeMaxDynamicSharedMemorySize,
                         GEMM_SMEM_BYTES);
    cudaFuncSetAttribute(flash_bf16, cudaFuncAttributeMaxDynamicSharedMemorySize,
                         FLASH_SMEM_BYTES);

    gemm_mma<0><<<dim3(N_QKV / BN, M_TOK / BM), 256, GEMM_SMEM_BYTES>>>(x, w_qkv, nullptr);
    flash_bf16<<<dim3(S_LEN / 128, H_NUM, B_SZ), 256, FLASH_SMEM_BYTES>>>();
    gemm_mma<1><<<dim3(E_DIM / BN, M_TOK / BM), 256, GEMM_SMEM_BYTES>>>(nullptr, w_comb, b_comb);
    ln_fused<<<M_TOK, 256>>>(x, gamma1, beta1, gamma2, beta2, theta, w1, b1,
                             (float*)d_out);
}

// round 8
// speedup vs baseline: 4.8887x; 1.1017x over previous
#include <cuda_runtime.h>
#include <cuda_bf16.h>
#include <cstdint>
#include <math.h>

// ---------------- problem constants ----------------
#define E_DIM  1024
#define H_NUM  16
#define DK_    64
#define B_SZ   2
#define S_LEN  2048
#define M_TOK  (B_SZ * S_LEN)       // 4096 tokens
#define N_QKV  (3 * E_DIM)          // 3072
#define K_DIM  1024

#define QSCALE (0.125f * 1.44269504088896f)   // 1/sqrt(dk) * log2(e)

// ---------------- device scratch (alloc-free) ----------------
__device__ __align__(16) __nv_bfloat16 g_qb[B_SZ * H_NUM * S_LEN * DK_];   // [B,H,S,dk] (xQSCALE)
__device__ __align__(16) __nv_bfloat16 g_kb[B_SZ * H_NUM * S_LEN * DK_];   // [B,H,S,dk]
__device__ __align__(16) __nv_bfloat16 g_vTb[B_SZ * H_NUM * DK_ * S_LEN];  // [B,H,dk,S]
__device__ float g_attn[M_TOK * E_DIM];               // [B,S,E]
__device__ float g_proj[M_TOK * E_DIM];               // [B,S,E]

__device__ __forceinline__ uint32_t packbf(float lo, float hi) {
    uint32_t r;
    asm("cvt.rn.bf16x2.f32 %0, %1, %2;" : "=r"(r) : "f"(hi), "f"(lo));
    return r;
}
__device__ __forceinline__ void mma_bf16(float c[4], const uint32_t a[4],
                                         const uint32_t b0, const uint32_t b1) {
    asm volatile(
        "mma.sync.aligned.m16n8k16.row.col.f32.bf16.bf16.f32 "
        "{%0,%1,%2,%3}, {%4,%5,%6,%7}, {%8,%9}, {%0,%1,%2,%3};"
        : "+f"(c[0]), "+f"(c[1]), "+f"(c[2]), "+f"(c[3])
        : "r"(a[0]), "r"(a[1]), "r"(a[2]), "r"(a[3]), "r"(b0), "r"(b1));
}

// ======================================================================
// bf16 mma.sync GEMM: C[M,N] = A[M,K] @ W[N,K]^T
// CTA 128x128, BK=32 (2 k-steps of 16), double-buffered.
// Smem layout per matrix stage (uint2): slab[kk]{514}[row]{x4}[la]
//   word(row,kk,la) = { bf16x2(A[row][16kk+2la..+1]), bf16x2(A[row][16kk+8+2la..+1]) }
// MODE 0: A = x, epilogue -> g_qb (xQSCALE) / g_kb / g_vTb (transposed)
// MODE 1: A = g_attn, +bias -> fp32 g_proj
// ======================================================================
#define SLAB 514
#define GST  (2 * SLAB)                   // uint2 per matrix stage = 1028
#define GEMM_SMEM_BYTES (4 * GST * 8)     // A[2] + B[2] = 32896 B

template <int MODE>
__global__ __launch_bounds__(256) void gemm_bf16(const float* __restrict__ Ain,
                                                 const float* __restrict__ W,
                                                 const float* __restrict__ bias)
{
    extern __shared__ uint2 sh[];
    uint2* As = sh;                        // [2][GST]
    uint2* Bs = sh + 2 * GST;              // [2][GST]

    const float* __restrict__ A = (MODE == 1) ? (const float*)g_attn : Ain;

    const int tid = threadIdx.x;
    const int wid = tid >> 5;
    const int lane = tid & 31;
    const int mu = lane >> 2;
    const int la = lane & 3;
    const int warp_m = wid & 1;
    const int warp_n = wid >> 1;
    const int m0 = blockIdx.y * 128;
    const int n0 = blockIdx.x * 128;

    const int ld_row = tid >> 1;           // 0..127
    const int ld_kk  = tid & 1;            // 0..1
    const int dst_i  = ld_kk * SLAB + ld_row * 4;
    const float* asrc = &A[(size_t)(m0 + ld_row) * K_DIM + ld_kk * 16];
    const float* wsrc = &W[(size_t)(n0 + ld_row) * K_DIM + ld_kk * 16];

    float acc[4][4][4];
#pragma unroll
    for (int mt = 0; mt < 4; mt++)
#pragma unroll
        for (int nt = 0; nt < 4; nt++)
#pragma unroll
            for (int e = 0; e < 4; e++) acc[mt][nt][e] = 0.f;

    // ---- stage chunk 0 ----
    {
        float4 f0 = *(const float4*)(asrc + 0),  f1 = *(const float4*)(asrc + 4);
        float4 f2 = *(const float4*)(asrc + 8),  f3 = *(const float4*)(asrc + 12);
        uint32_t w0 = packbf(f0.x, f0.y), w1 = packbf(f0.z, f0.w);
        uint32_t w2 = packbf(f1.x, f1.y), w3 = packbf(f1.z, f1.w);
        uint32_t w4 = packbf(f2.x, f2.y), w5 = packbf(f2.z, f2.w);
        uint32_t w6 = packbf(f3.x, f3.y), w7 = packbf(f3.z, f3.w);
        *(uint4*)&As[dst_i]     = make_uint4(w0, w4, w1, w5);
        *(uint4*)&As[dst_i + 2] = make_uint4(w2, w6, w3, w7);
        f0 = *(const float4*)(wsrc + 0);  f1 = *(const float4*)(wsrc + 4);
        f2 = *(const float4*)(wsrc + 8);  f3 = *(const float4*)(wsrc + 12);
        w0 = packbf(f0.x, f0.y); w1 = packbf(f0.z, f0.w);
        w2 = packbf(f1.x, f1.y); w3 = packbf(f1.z, f1.w);
        w4 = packbf(f2.x, f2.y); w5 = packbf(f2.z, f2.w);
        w6 = packbf(f3.x, f3.y); w7 = packbf(f3.z, f3.w);
        *(uint4*)&Bs[dst_i]     = make_uint4(w0, w4, w1, w5);
        *(uint4*)&Bs[dst_i + 2] = make_uint4(w2, w6, w3, w7);
    }
    __syncthreads();

    const int NK = K_DIM / 32;             // 32
    for (int t = 0; t < NK; t++) {
        const int s = t & 1;
        const uint2* Asl = As + s * GST;
        const uint2* Bsl = Bs + s * GST;

        // prefetch next chunk
        float4 pa[4], pw[4];
        if (t + 1 < NK) {
            const int k0 = (t + 1) * 32;
#pragma unroll
            for (int i = 0; i < 4; i++) {
                pa[i] = *(const float4*)(asrc + k0 + i * 4);
                pw[i] = *(const float4*)(wsrc + k0 + i * 4);
            }
        }

        // compute: 2 k-steps of 16
#pragma unroll
        for (int kk = 0; kk < 2; kk++) {
            uint32_t afr[4][4];
#pragma unroll
            for (int mt = 0; mt < 4; mt++) {
                const int r0 = warp_m * 64 + mt * 16 + mu;
                uint2 ua = Asl[kk * SLAB + r0 * 4 + la];
                uint2 ub = Asl[kk * SLAB + (r0 + 8) * 4 + la];
                afr[mt][0] = ua.x; afr[mt][1] = ub.x;
                afr[mt][2] = ua.y; afr[mt][3] = ub.y;
            }
            uint2 bfr[4];
#pragma unroll
            for (int nt = 0; nt < 4; nt++) {
                const int n = warp_n * 32 + nt * 8 + mu;
                bfr[nt] = Bsl[kk * SLAB + n * 4 + la];
            }
#pragma unroll
            for (int mt = 0; mt < 4; mt++)
#pragma unroll
                for (int nt = 0; nt < 4; nt++)
                    mma_bf16(acc[mt][nt], afr[mt], bfr[nt].x, bfr[nt].y);
        }
        __syncthreads();

        // store prefetched chunk
        if (t + 1 < NK) {
            uint2* Asn = As + (s ^ 1) * GST;
            uint2* Bsn = Bs + (s ^ 1) * GST;
            uint32_t w0 = packbf(pa[0].x, pa[0].y), w1 = packbf(pa[0].z, pa[0].w);
            uint32_t w2 = packbf(pa[1].x, pa[1].y), w3 = packbf(pa[1].z, pa[1].w);
            uint32_t w4 = packbf(pa[2].x, pa[2].y), w5 = packbf(pa[2].z, pa[2].w);
            uint32_t w6 = packbf(pa[3].x, pa[3].y), w7 = packbf(pa[3].z, pa[3].w);
            *(uint4*)&Asn[dst_i]     = make_uint4(w0, w4, w1, w5);
            *(uint4*)&Asn[dst_i + 2] = make_uint4(w2, w6, w3, w7);
            w0 = packbf(pw[0].x, pw[0].y); w1 = packbf(pw[0].z, pw[0].w);
            w2 = packbf(pw[1].x, pw[1].y); w3 = packbf(pw[1].z, pw[1].w);
            w4 = packbf(pw[2].x, pw[2].y); w5 = packbf(pw[2].z, pw[2].w);
            w6 = packbf(pw[3].x, pw[3].y); w7 = packbf(pw[3].z, pw[3].w);
            *(uint4*)&Bsn[dst_i]     = make_uint4(w0, w4, w1, w5);
            *(uint4*)&Bsn[dst_i + 2] = make_uint4(w2, w6, w3, w7);
            __syncthreads();
        }
    }

    // ---- epilogue ----
#pragma unroll
    for (int mt = 0; mt < 4; mt++) {
        const int m_lo = m0 + warp_m * 64 + mt * 16 + mu;
        const int m_hi = m_lo + 8;
#pragma unroll
        for (int nt = 0; nt < 4; nt++) {
            const int n = n0 + warp_n * 32 + nt * 8 + 2 * la;
            if (MODE == 0) {
                const int which = n >> 10;
                const int h = (n >> 6) & 15;
                const int d0 = n & 63;
                const int b = m_lo >> 11;
                const int s_lo = m_lo & 2047, s_hi = m_hi & 2047;
                if (which == 0) {
                    size_t base = (((size_t)(b * H_NUM + h)) * S_LEN);
                    *(__nv_bfloat162*)&g_qb[(base + s_lo) * DK_ + d0] =
                        __floats2bfloat162_rn(acc[mt][nt][0] * QSCALE,
                                              acc[mt][nt][1] * QSCALE);
                    *(__nv_bfloat162*)&g_qb[(base + s_hi) * DK_ + d0] =
                        __floats2bfloat162_rn(acc[mt][nt][2] * QSCALE,
                                              acc[mt][nt][3] * QSCALE);
                } else if (which == 1) {
                    size_t base = (((size_t)(b * H_NUM + h)) * S_LEN);
                    *(__nv_bfloat162*)&g_kb[(base + s_lo) * DK_ + d0] =
                        __floats2bfloat162_rn(acc[mt][nt][0], acc[mt][nt][1]);
                    *(__nv_bfloat162*)&g_kb[(base + s_hi) * DK_ + d0] =
                        __floats2bfloat162_rn(acc[mt][nt][2], acc[mt][nt][3]);
                } else {
                    size_t base = (((size_t)(b * H_NUM + h)) * DK_ + d0) * S_LEN;
                    g_vTb[base + s_lo]          = __float2bfloat16_rn(acc[mt][nt][0]);
                    g_vTb[base + S_LEN + s_lo]  = __float2bfloat16_rn(acc[mt][nt][1]);
                    g_vTb[base + s_hi]          = __float2bfloat16_rn(acc[mt][nt][2]);
                    g_vTb[base + S_LEN + s_hi]  = __float2bfloat16_rn(acc[mt][nt][3]);
                }
            } else {
                const float b0 = bias[n], b1 = bias[n + 1];
                *(float2*)&g_proj[(size_t)m_lo * E_DIM + n] =
                    make_float2(acc[mt][nt][0] + b0, acc[mt][nt][1] + b1);
                *(float2*)&g_proj[(size_t)m_hi * E_DIM + n] =
                    make_float2(acc[mt][nt][2] + b0, acc[mt][nt][3] + b1);
            }
        }
    }
}

// ======================================================================
// Flash attention, bf16 m16n8k16, register-resident P, exp2-domain softmax
// (Q pre-scaled by 0.125*log2e in GEMM1 epilogue).
// ======================================================================
#define FKB 1028                       // 4 kk-slabs * 257
#define FLASH_U2 (4 * FKB + 128 * 20)
#define FLASH_SMEM_BYTES (FLASH_U2 * 8)

__global__ __launch_bounds__(256, 2) void flash_bf16()
{
    extern __shared__ uint2 fsm[];
    uint2* Qp = fsm + 4 * FKB;

    const int tid = threadIdx.x;
    const int wid = tid >> 5;
    const int lane = tid & 31;
    const int mu = lane >> 2;
    const int la = lane & 3;
    const int b = blockIdx.z, h = blockIdx.y;
    const int q0 = blockIdx.x * 128;
    const size_t hoff = ((size_t)(b * H_NUM + h)) * S_LEN * DK_;

    const int kkk = tid & 3, kkey = tid >> 2;
    const __nv_bfloat16* ksrc = g_kb + hoff + (size_t)kkey * DK_ + kkk * 16;
    const int vkk = tid & 3, vd = tid >> 2;
    const __nv_bfloat16* vsrc = g_vTb + hoff + (size_t)vd * S_LEN + vkk * 16;
    const int kdst_i = kkk * 257 + kkey * 4;
    const int vdst_i = vkk * 257 + vd * 4;

#pragma unroll
    for (int it = 0; it < 2; it++) {
        int item = tid + it * 256;
        int row = item >> 2, kk = item & 3;
        const __nv_bfloat16* qs = g_qb + hoff + (size_t)(q0 + row) * DK_ + kk * 16;
        uint4 u0 = *(const uint4*)qs;
        uint4 u1 = *(const uint4*)(qs + 8);
        uint2* dst = Qp + row * 20 + kk * 4;
        dst[0] = make_uint2(u0.x, u1.x);
        dst[1] = make_uint2(u0.y, u1.y);
        dst[2] = make_uint2(u0.z, u1.z);
        dst[3] = make_uint2(u0.w, u1.w);
    }
    {
        uint4 k0a = *(const uint4*)ksrc;
        uint4 k0b = *(const uint4*)(ksrc + 8);
        uint4 v0a = *(const uint4*)vsrc;
        uint4 v0b = *(const uint4*)(vsrc + 8);
        uint2* kd = fsm + kdst_i;
        kd[0] = make_uint2(k0a.x, k0b.x); kd[1] = make_uint2(k0a.y, k0b.y);
        kd[2] = make_uint2(k0a.z, k0b.z); kd[3] = make_uint2(k0a.w, k0b.w);
        uint2* vdp = fsm + 2 * FKB + vdst_i;
        vdp[0] = make_uint2(v0a.x, v0b.x); vdp[1] = make_uint2(v0a.y, v0b.y);
        vdp[2] = make_uint2(v0a.z, v0b.z); vdp[3] = make_uint2(v0a.w, v0b.w);
    }
    __syncthreads();

    uint32_t qf[4][4];
    {
        const int r0 = wid * 16 + mu;
#pragma unroll
        for (int kk = 0; kk < 4; kk++) {
            uint2 qa = Qp[r0 * 20 + kk * 4 + la];
            uint2 qb = Qp[(r0 + 8) * 20 + kk * 4 + la];
            qf[kk][0] = qa.x; qf[kk][1] = qb.x;
            qf[kk][2] = qa.y; qf[kk][3] = qb.y;
        }
    }

    float m0 = -1e30f, m1 = -1e30f, l0 = 0.f, l1 = 0.f;
    float acc[8][4];
#pragma unroll
    for (int j = 0; j < 8; j++)
#pragma unroll
        for (int e = 0; e < 4; e++) acc[j][e] = 0.f;

    const int NCH = S_LEN / 64;
    for (int kt = 0; kt < NCH; kt++) {
        const uint2* Kc = fsm + (kt & 1) * FKB;
        const uint2* Vc = fsm + 2 * FKB + (kt & 1) * FKB;

        uint4 ku0, ku1, vu0, vu1;
        const bool more = (kt + 1 < NCH);
        if (more) {
            const __nv_bfloat16* ks = ksrc + (size_t)(kt + 1) * 64 * DK_;
            const __nv_bfloat16* vs = vsrc + (size_t)(kt + 1) * 64;
            ku0 = *(const uint4*)ks; ku1 = *(const uint4*)(ks + 8);
            vu0 = *(const uint4*)vs; vu1 = *(const uint4*)(vs + 8);
        }

        // ---- S = Q @ K^T (log2-domain scores) ----
        float s[8][4];
#pragma unroll
        for (int j = 0; j < 8; j++)
#pragma unroll
            for (int e = 0; e < 4; e++) s[j][e] = 0.f;
#pragma unroll
        for (int kk = 0; kk < 4; kk++) {
#pragma unroll
            for (int j = 0; j < 8; j++) {
                uint2 kb = Kc[kk * 257 + (j * 8 + mu) * 4 + la];
                mma_bf16(s[j], qf[kk], kb.x, kb.y);
            }
        }

        // ---- online softmax in base-2 ----
        float mx0 = -1e30f, mx1 = -1e30f;
#pragma unroll
        for (int j = 0; j < 8; j++) {
            mx0 = fmaxf(mx0, fmaxf(s[j][0], s[j][1]));
            mx1 = fmaxf(mx1, fmaxf(s[j][2], s[j][3]));
        }
        mx0 = fmaxf(mx0, __shfl_xor_sync(0xffffffffu, mx0, 1));
        mx0 = fmaxf(mx0, __shfl_xor_sync(0xffffffffu, mx0, 2));
        mx1 = fmaxf(mx1, __shfl_xor_sync(0xffffffffu, mx1, 1));
        mx1 = fmaxf(mx1, __shfl_xor_sync(0xffffffffu, mx1, 2));
        const float nm0 = fmaxf(m0, mx0), nm1 = fmaxf(m1, mx1);
        float sum0 = 0.f, sum1 = 0.f;
#pragma unroll
        for (int j = 0; j < 8; j++) {
            s[j][0] = exp2f(s[j][0] - nm0);
            s[j][1] = exp2f(s[j][1] - nm0);
            s[j][2] = exp2f(s[j][2] - nm1);
            s[j][3] = exp2f(s[j][3] - nm1);
            sum0 += s[j][0] + s[j][1];
            sum1 += s[j][2] + s[j][3];
        }
        sum0 += __shfl_xor_sync(0xffffffffu, sum0, 1);
        sum0 += __shfl_xor_sync(0xffffffffu, sum0, 2);
        sum1 += __shfl_xor_sync(0xffffffffu, sum1, 1);
        sum1 += __shfl_xor_sync(0xffffffffu, sum1, 2);
        const float sc0 = exp2f(m0 - nm0), sc1 = exp2f(m1 - nm1);
#pragma unroll
        for (int j = 0; j < 8; j++) {
            acc[j][0] *= sc0; acc[j][1] *= sc0;
            acc[j][2] *= sc1; acc[j][3] *= sc1;
        }
        l0 = l0 * sc0 + sum0; l1 = l1 * sc1 + sum1;
        m0 = nm0; m1 = nm1;

        // ---- pack P to A-fragments ----
        uint32_t pf[4][4];
#pragma unroll
        for (int kk = 0; kk < 4; kk++) {
            pf[kk][0] = packbf(s[2 * kk][0],     s[2 * kk][1]);
            pf[kk][1] = packbf(s[2 * kk][2],     s[2 * kk][3]);
            pf[kk][2] = packbf(s[2 * kk + 1][0], s[2 * kk + 1][1]);
            pf[kk][3] = packbf(s[2 * kk + 1][2], s[2 * kk + 1][3]);
        }

        // ---- O += P @ V ----
#pragma unroll
        for (int kk = 0; kk < 4; kk++) {
#pragma unroll
            for (int j = 0; j < 8; j++) {
                uint2 vb = Vc[kk * 257 + (j * 8 + mu) * 4 + la];
                mma_bf16(acc[j], pf[kk], vb.x, vb.y);
            }
        }

        if (more) {
            uint2* kd = fsm + ((kt + 1) & 1) * FKB + kdst_i;
            kd[0] = make_uint2(ku0.x, ku1.x); kd[1] = make_uint2(ku0.y, ku1.y);
            kd[2] = make_uint2(ku0.z, ku1.z); kd[3] = make_uint2(ku0.w, ku1.w);
            uint2* vdp = fsm + 2 * FKB + ((kt + 1) & 1) * FKB + vdst_i;
            vdp[0] = make_uint2(vu0.x, vu1.x); vdp[1] = make_uint2(vu0.y, vu1.y);
            vdp[2] = make_uint2(vu0.z, vu1.z); vdp[3] = make_uint2(vu0.w, vu1.w);
        }
        __syncthreads();
    }

    const float i0 = 1.f / l0, i1 = 1.f / l1;
    const int row_a = q0 + wid * 16 + mu;
    const int row_b = row_a + 8;
    float* oa = &g_attn[((size_t)b * S_LEN + row_a) * E_DIM + h * DK_];
    float* ob = &g_attn[((size_t)b * S_LEN + row_b) * E_DIM + h * DK_];
#pragma unroll
    for (int j = 0; j < 8; j++) {
        const int c = j * 8 + 2 * la;
        *(float2*)&oa[c] = make_float2(acc[j][0] * i0, acc[j][1] * i0);
        *(float2*)&ob[c] = make_float2(acc[j][2] * i1, acc[j][3] * i1);
    }
}

// ======================================================================
// Fused LN1 + quantum FFN + LN2 — float4 vectorized.
// Thread t handles cols 4t..4t+3.
// ======================================================================
__global__ __launch_bounds__(256) void ln_fused(const float* __restrict__ x,
                                                const float* __restrict__ g1,
                                                const float* __restrict__ be1,
                                                const float* __restrict__ g2,
                                                const float* __restrict__ be2,
                                                const float* __restrict__ theta,
                                                const float* __restrict__ w1,
                                                const float* __restrict__ b1s,
                                                float* __restrict__ out)
{
    const int row = blockIdx.x;
    const int tid = threadIdx.x;
    const float* xr = x + (size_t)row * E_DIM;
    const float* pr = g_proj + (size_t)row * E_DIM;

    __shared__ float red[16];
    __shared__ float sx1[8];

    float4 xv = *(const float4*)&xr[tid * 4];
    float4 pv = *(const float4*)&pr[tid * 4];
    float v[4] = {xv.x + pv.x, xv.y + pv.y, xv.z + pv.z, xv.w + pv.w};

    float s = 0.f, ss = 0.f;
#pragma unroll
    for (int i = 0; i < 4; i++) { s += v[i]; ss += v[i] * v[i]; }
#pragma unroll
    for (int o = 16; o > 0; o >>= 1) {
        s  += __shfl_xor_sync(0xffffffffu, s, o);
        ss += __shfl_xor_sync(0xffffffffu, ss, o);
    }
    if ((tid & 31) == 0) { red[tid >> 5] = s; red[8 + (tid >> 5)] = ss; }
    __syncthreads();
    s = 0.f; ss = 0.f;
#pragma unroll
    for (int w = 0; w < 8; w++) { s += red[w]; ss += red[8 + w]; }
    float mean = s * (1.f / E_DIM);
    float var  = ss * (1.f / E_DIM) - mean * mean;
    float rs = rsqrtf(var + 1e-5f);

    float4 g1v = *(const float4*)&g1[tid * 4];
    float4 b1v = *(const float4*)&be1[tid * 4];
    float x1[4];
    x1[0] = (v[0] - mean) * rs * g1v.x + b1v.x;
    x1[1] = (v[1] - mean) * rs * g1v.y + b1v.y;
    x1[2] = (v[2] - mean) * rs * g1v.z + b1v.z;
    x1[3] = (v[3] - mean) * rs * g1v.w + b1v.w;
    if (tid < 2) {
#pragma unroll
        for (int i = 0; i < 4; i++) sx1[tid * 4 + i] = x1[i];
    }
    __syncthreads();

    float f = b1s[0];
#pragma unroll
    for (int q = 0; q < 8; q++) f += __cosf(sx1[q]) * __cosf(theta[q]) * w1[q];

    float y[4];
    s = 0.f; ss = 0.f;
#pragma unroll
    for (int i = 0; i < 4; i++) { y[i] = x1[i] + f; s += y[i]; ss += y[i] * y[i]; }
#pragma unroll
    for (int o = 16; o > 0; o >>= 1) {
        s  += __shfl_xor_sync(0xffffffffu, s, o);
        ss += __shfl_xor_sync(0xffffffffu, ss, o);
    }
    if ((tid & 31) == 0) { red[tid >> 5] = s; red[8 + (tid >> 5)] = ss; }
    __syncthreads();
    s = 0.f; ss = 0.f;
#pragma unroll
    for (int w = 0; w < 8; w++) { s += red[w]; ss += red[8 + w]; }
    float mean2 = s * (1.f / E_DIM);
    float var2  = ss * (1.f / E_DIM) - mean2 * mean2;
    float rs2 = rsqrtf(var2 + 1e-5f);

    float4 g2v = *(const float4*)&g2[tid * 4];
    float4 b2v = *(const float4*)&be2[tid * 4];
    float4 ov;
    ov.x = (y[0] - mean2) * rs2 * g2v.x + b2v.x;
    ov.y = (y[1] - mean2) * rs2 * g2v.y + b2v.y;
    ov.z = (y[2] - mean2) * rs2 * g2v.z + b2v.z;
    ov.w = (y[3] - mean2) * rs2 * g2v.w + b2v.w;
    *(float4*)&out[(size_t)row * E_DIM + tid * 4] = ov;
}

// ======================================================================
extern "C" void kernel_launch(void* const* d_in, const int* in_sizes, int n_in,
                              void* d_out, int out_size)
{
    const float* x      = (const float*)d_in[0];
    const float* w_qkv  = (const float*)d_in[1];
    const float* w_comb = (const float*)d_in[2];
    const float* b_comb = (const float*)d_in[3];
    const float* gamma1 = (const float*)d_in[4];
    const float* beta1  = (const float*)d_in[5];
    const float* gamma2 = (const float*)d_in[6];
    const float* beta2  = (const float*)d_in[7];
    const float* theta  = (const float*)d_in[8];
    const float* w1     = (const float*)d_in[9];
    const float* b1     = (const float*)d_in[10];

    cudaFuncSetAttribute(gemm_bf16<0>, cudaFuncAttributeMaxDynamicSharedMemorySize,
                         GEMM_SMEM_BYTES);
    cudaFuncSetAttribute(gemm_bf16<1>, cudaFuncAttributeMaxDynamicSharedMemorySize,
                         GEMM_SMEM_BYTES);
    cudaFuncSetAttribute(flash_bf16, cudaFuncAttributeMaxDynamicSharedMemorySize,
                         FLASH_SMEM_BYTES);

    gemm_bf16<0><<<dim3(N_QKV / 128, M_TOK / 128), 256, GEMM_SMEM_BYTES>>>(x, w_qkv, nullptr);
    flash_bf16<<<dim3(S_LEN / 128, H_NUM, B_SZ), 256, FLASH_SMEM_BYTES>>>();
    gemm_bf16<1><<<dim3(E_DIM / 128, M_TOK / 128), 256, GEMM_SMEM_BYTES>>>(nullptr, w_comb, b_comb);
    ln_fused<<<M_TOK, 256>>>(x, gamma1, beta1, gamma2, beta2, theta, w1, b1,
                             (float*)d_out);
}

// round 9
// speedup vs baseline: 5.7097x; 1.1679x over previous
#include <cuda_runtime.h>
#include <cuda_bf16.h>
#include <cstdint>
#include <math.h>

// ---------------- problem constants ----------------
#define E_DIM  1024
#define H_NUM  16
#define DK_    64
#define B_SZ   2
#define S_LEN  2048
#define M_TOK  (B_SZ * S_LEN)       // 4096 tokens
#define N_QKV  (3 * E_DIM)          // 3072
#define K_DIM  1024

#define QSCALE (0.125f * 1.44269504088896f)   // 1/sqrt(dk) * log2(e)

// ---------------- device scratch (alloc-free) ----------------
__device__ __align__(16) __nv_bfloat16 g_xb[M_TOK * K_DIM];                // bf16 x
__device__ __align__(16) __nv_bfloat16 g_wqb[N_QKV * K_DIM];               // bf16 w_qkv
__device__ __align__(16) __nv_bfloat16 g_wcb[E_DIM * K_DIM];               // bf16 w_comb
__device__ __align__(16) __nv_bfloat16 g_qb[B_SZ * H_NUM * S_LEN * DK_];   // [B,H,S,dk] (xQSCALE)
__device__ __align__(16) __nv_bfloat16 g_kb[B_SZ * H_NUM * S_LEN * DK_];   // [B,H,S,dk]
__device__ __align__(16) __nv_bfloat16 g_vTb[B_SZ * H_NUM * DK_ * S_LEN];  // [B,H,dk,S]
__device__ __align__(16) __nv_bfloat16 g_attnb[M_TOK * E_DIM];             // bf16 [B,S,E]
__device__ float g_proj[M_TOK * E_DIM];                                    // fp32 [B,S,E]

__device__ __forceinline__ uint32_t packbf(float lo, float hi) {
    uint32_t r;
    asm("cvt.rn.bf16x2.f32 %0, %1, %2;" : "=r"(r) : "f"(hi), "f"(lo));
    return r;
}
__device__ __forceinline__ void mma_bf16(float c[4], const uint32_t a[4],
                                         const uint32_t b0, const uint32_t b1) {
    asm volatile(
        "mma.sync.aligned.m16n8k16.row.col.f32.bf16.bf16.f32 "
        "{%0,%1,%2,%3}, {%4,%5,%6,%7}, {%8,%9}, {%0,%1,%2,%3};"
        : "+f"(c[0]), "+f"(c[1]), "+f"(c[2]), "+f"(c[3])
        : "r"(a[0]), "r"(a[1]), "r"(a[2]), "r"(a[3]), "r"(b0), "r"(b1));
}

// ======================================================================
// fp32 -> bf16 bulk convert (8 elements/thread)
// ======================================================================
__global__ __launch_bounds__(256) void conv_bf16(const float* __restrict__ src,
                                                 __nv_bfloat16* __restrict__ dst,
                                                 int n8)
{
    int i = blockIdx.x * 256 + threadIdx.x;
    if (i >= n8) return;
    float4 a = *(const float4*)&src[i * 8];
    float4 b = *(const float4*)&src[i * 8 + 4];
    uint4 o = make_uint4(packbf(a.x, a.y), packbf(a.z, a.w),
                         packbf(b.x, b.y), packbf(b.z, b.w));
    *(uint4*)&dst[i * 8] = o;
}

// ======================================================================
// bf16 mma.sync GEMM with bf16 operands: C[M,N] = A[M,K] @ W[N,K]^T
// CTA 128x128, BK=32 (2 k-steps of 16), double-buffered.
// Smem per matrix stage (uint2): slab[kk]{514}[row]{x4}[la]
//   uint2(row,kk,la) = { bf16x2 @k=16kk+2la, bf16x2 @k=16kk+8+2la }
// MODE 0: A = g_xb, W = g_wqb -> g_qb (xQSCALE) / g_kb / g_vTb
// MODE 1: A = g_attnb, W = g_wcb, +bias -> fp32 g_proj
// ======================================================================
#define SLAB 514
#define GST  (2 * SLAB)
#define GEMM_SMEM_BYTES (4 * GST * 8)     // 32896 B

template <int MODE>
__global__ __launch_bounds__(256) void gemm_bf16(const float* __restrict__ bias)
{
    extern __shared__ uint2 sh[];
    uint2* As = sh;
    uint2* Bs = sh + 2 * GST;

    const __nv_bfloat16* __restrict__ A = (MODE == 1) ? g_attnb : g_xb;
    const __nv_bfloat16* __restrict__ W = (MODE == 1) ? g_wcb : g_wqb;

    const int tid = threadIdx.x;
    const int wid = tid >> 5;
    const int lane = tid & 31;
    const int mu = lane >> 2;
    const int la = lane & 3;
    const int warp_m = wid & 1;
    const int warp_n = wid >> 1;
    const int m0 = blockIdx.y * 128;
    const int n0 = blockIdx.x * 128;

    const int ld_row = tid >> 1;           // 0..127
    const int ld_kk  = tid & 1;            // 0..1
    const int dst_i  = ld_kk * SLAB + ld_row * 4;
    const __nv_bfloat16* asrc = &A[(size_t)(m0 + ld_row) * K_DIM + ld_kk * 16];
    const __nv_bfloat16* wsrc = &W[(size_t)(n0 + ld_row) * K_DIM + ld_kk * 16];

    float acc[4][4][4];
#pragma unroll
    for (int mt = 0; mt < 4; mt++)
#pragma unroll
        for (int nt = 0; nt < 4; nt++)
#pragma unroll
            for (int e = 0; e < 4; e++) acc[mt][nt][e] = 0.f;

    // ---- stage chunk 0 ----
    {
        uint4 a0 = *(const uint4*)asrc;          // words w0..w3
        uint4 a1 = *(const uint4*)(asrc + 8);    // words w4..w7
        *(uint4*)&As[dst_i]     = make_uint4(a0.x, a1.x, a0.y, a1.y);
        *(uint4*)&As[dst_i + 2] = make_uint4(a0.z, a1.z, a0.w, a1.w);
        uint4 b0 = *(const uint4*)wsrc;
        uint4 b1 = *(const uint4*)(wsrc + 8);
        *(uint4*)&Bs[dst_i]     = make_uint4(b0.x, b1.x, b0.y, b1.y);
        *(uint4*)&Bs[dst_i + 2] = make_uint4(b0.z, b1.z, b0.w, b1.w);
    }
    __syncthreads();

    const int NK = K_DIM / 32;             // 32
    for (int t = 0; t < NK; t++) {
        const int s = t & 1;
        const uint2* Asl = As + s * GST;
        const uint2* Bsl = Bs + s * GST;

        uint4 pa0, pa1, pw0, pw1;
        if (t + 1 < NK) {
            const int k0 = (t + 1) * 32;
            pa0 = *(const uint4*)(asrc + k0);
            pa1 = *(const uint4*)(asrc + k0 + 8);
            pw0 = *(const uint4*)(wsrc + k0);
            pw1 = *(const uint4*)(wsrc + k0 + 8);
        }

#pragma unroll
        for (int kk = 0; kk < 2; kk++) {
            uint32_t afr[4][4];
#pragma unroll
            for (int mt = 0; mt < 4; mt++) {
                const int r0 = warp_m * 64 + mt * 16 + mu;
                uint2 ua = Asl[kk * SLAB + r0 * 4 + la];
                uint2 ub = Asl[kk * SLAB + (r0 + 8) * 4 + la];
                afr[mt][0] = ua.x; afr[mt][1] = ub.x;
                afr[mt][2] = ua.y; afr[mt][3] = ub.y;
            }
            uint2 bfr[4];
#pragma unroll
            for (int nt = 0; nt < 4; nt++) {
                const int n = warp_n * 32 + nt * 8 + mu;
                bfr[nt] = Bsl[kk * SLAB + n * 4 + la];
            }
#pragma unroll
            for (int mt = 0; mt < 4; mt++)
#pragma unroll
                for (int nt = 0; nt < 4; nt++)
                    mma_bf16(acc[mt][nt], afr[mt], bfr[nt].x, bfr[nt].y);
        }
        __syncthreads();

        if (t + 1 < NK) {
            uint2* Asn = As + (s ^ 1) * GST;
            uint2* Bsn = Bs + (s ^ 1) * GST;
            *(uint4*)&Asn[dst_i]     = make_uint4(pa0.x, pa1.x, pa0.y, pa1.y);
            *(uint4*)&Asn[dst_i + 2] = make_uint4(pa0.z, pa1.z, pa0.w, pa1.w);
            *(uint4*)&Bsn[dst_i]     = make_uint4(pw0.x, pw1.x, pw0.y, pw1.y);
            *(uint4*)&Bsn[dst_i + 2] = make_uint4(pw0.z, pw1.z, pw0.w, pw1.w);
            __syncthreads();
        }
    }

    // ---- epilogue ----
#pragma unroll
    for (int mt = 0; mt < 4; mt++) {
        const int m_lo = m0 + warp_m * 64 + mt * 16 + mu;
        const int m_hi = m_lo + 8;
#pragma unroll
        for (int nt = 0; nt < 4; nt++) {
            const int n = n0 + warp_n * 32 + nt * 8 + 2 * la;
            if (MODE == 0) {
                const int which = n >> 10;
                const int h = (n >> 6) & 15;
                const int d0 = n & 63;
                const int b = m_lo >> 11;
                const int s_lo = m_lo & 2047, s_hi = m_hi & 2047;
                if (which == 0) {
                    size_t base = (((size_t)(b * H_NUM + h)) * S_LEN);
                    *(uint32_t*)&g_qb[(base + s_lo) * DK_ + d0] =
                        packbf(acc[mt][nt][0] * QSCALE, acc[mt][nt][1] * QSCALE);
                    *(uint32_t*)&g_qb[(base + s_hi) * DK_ + d0] =
                        packbf(acc[mt][nt][2] * QSCALE, acc[mt][nt][3] * QSCALE);
                } else if (which == 1) {
                    size_t base = (((size_t)(b * H_NUM + h)) * S_LEN);
                    *(uint32_t*)&g_kb[(base + s_lo) * DK_ + d0] =
                        packbf(acc[mt][nt][0], acc[mt][nt][1]);
                    *(uint32_t*)&g_kb[(base + s_hi) * DK_ + d0] =
                        packbf(acc[mt][nt][2], acc[mt][nt][3]);
                } else {
                    size_t base = (((size_t)(b * H_NUM + h)) * DK_ + d0) * S_LEN;
                    g_vTb[base + s_lo]          = __float2bfloat16_rn(acc[mt][nt][0]);
                    g_vTb[base + S_LEN + s_lo]  = __float2bfloat16_rn(acc[mt][nt][1]);
                    g_vTb[base + s_hi]          = __float2bfloat16_rn(acc[mt][nt][2]);
                    g_vTb[base + S_LEN + s_hi]  = __float2bfloat16_rn(acc[mt][nt][3]);
                }
            } else {
                const float b0 = bias[n], b1 = bias[n + 1];
                *(float2*)&g_proj[(size_t)m_lo * E_DIM + n] =
                    make_float2(acc[mt][nt][0] + b0, acc[mt][nt][1] + b1);
                *(float2*)&g_proj[(size_t)m_hi * E_DIM + n] =
                    make_float2(acc[mt][nt][2] + b0, acc[mt][nt][3] + b1);
            }
        }
    }
}

// ======================================================================
// Flash attention, bf16 m16n8k16, register-resident P, exp2-domain softmax.
// Output written as bf16 into g_attnb.
// ======================================================================
#define FKB 1028
#define FLASH_U2 (4 * FKB + 128 * 20)
#define FLASH_SMEM_BYTES (FLASH_U2 * 8)

__global__ __launch_bounds__(256, 2) void flash_bf16()
{
    extern __shared__ uint2 fsm[];
    uint2* Qp = fsm + 4 * FKB;

    const int tid = threadIdx.x;
    const int wid = tid >> 5;
    const int lane = tid & 31;
    const int mu = lane >> 2;
    const int la = lane & 3;
    const int b = blockIdx.z, h = blockIdx.y;
    const int q0 = blockIdx.x * 128;
    const size_t hoff = ((size_t)(b * H_NUM + h)) * S_LEN * DK_;

    const int kkk = tid & 3, kkey = tid >> 2;
    const __nv_bfloat16* ksrc = g_kb + hoff + (size_t)kkey * DK_ + kkk * 16;
    const int vkk = tid & 3, vd = tid >> 2;
    const __nv_bfloat16* vsrc = g_vTb + hoff + (size_t)vd * S_LEN + vkk * 16;
    const int kdst_i = kkk * 257 + kkey * 4;
    const int vdst_i = vkk * 257 + vd * 4;

#pragma unroll
    for (int it = 0; it < 2; it++) {
        int item = tid + it * 256;
        int row = item >> 2, kk = item & 3;
        const __nv_bfloat16* qs = g_qb + hoff + (size_t)(q0 + row) * DK_ + kk * 16;
        uint4 u0 = *(const uint4*)qs;
        uint4 u1 = *(const uint4*)(qs + 8);
        uint2* dst = Qp + row * 20 + kk * 4;
        dst[0] = make_uint2(u0.x, u1.x);
        dst[1] = make_uint2(u0.y, u1.y);
        dst[2] = make_uint2(u0.z, u1.z);
        dst[3] = make_uint2(u0.w, u1.w);
    }
    {
        uint4 k0a = *(const uint4*)ksrc;
        uint4 k0b = *(const uint4*)(ksrc + 8);
        uint4 v0a = *(const uint4*)vsrc;
        uint4 v0b = *(const uint4*)(vsrc + 8);
        uint2* kd = fsm + kdst_i;
        kd[0] = make_uint2(k0a.x, k0b.x); kd[1] = make_uint2(k0a.y, k0b.y);
        kd[2] = make_uint2(k0a.z, k0b.z); kd[3] = make_uint2(k0a.w, k0b.w);
        uint2* vdp = fsm + 2 * FKB + vdst_i;
        vdp[0] = make_uint2(v0a.x, v0b.x); vdp[1] = make_uint2(v0a.y, v0b.y);
        vdp[2] = make_uint2(v0a.z, v0b.z); vdp[3] = make_uint2(v0a.w, v0b.w);
    }
    __syncthreads();

    uint32_t qf[4][4];
    {
        const int r0 = wid * 16 + mu;
#pragma unroll
        for (int kk = 0; kk < 4; kk++) {
            uint2 qa = Qp[r0 * 20 + kk * 4 + la];
            uint2 qb = Qp[(r0 + 8) * 20 + kk * 4 + la];
            qf[kk][0] = qa.x; qf[kk][1] = qb.x;
            qf[kk][2] = qa.y; qf[kk][3] = qb.y;
        }
    }

    float m0 = -1e30f, m1 = -1e30f, l0 = 0.f, l1 = 0.f;
    float acc[8][4];
#pragma unroll
    for (int j = 0; j < 8; j++)
#pragma unroll
        for (int e = 0; e < 4; e++) acc[j][e] = 0.f;

    const int NCH = S_LEN / 64;
    for (int kt = 0; kt < NCH; kt++) {
        const uint2* Kc = fsm + (kt & 1) * FKB;
        const uint2* Vc = fsm + 2 * FKB + (kt & 1) * FKB;

        uint4 ku0, ku1, vu0, vu1;
        const bool more = (kt + 1 < NCH);
        if (more) {
            const __nv_bfloat16* ks = ksrc + (size_t)(kt + 1) * 64 * DK_;
            const __nv_bfloat16* vs = vsrc + (size_t)(kt + 1) * 64;
            ku0 = *(const uint4*)ks; ku1 = *(const uint4*)(ks + 8);
            vu0 = *(const uint4*)vs; vu1 = *(const uint4*)(vs + 8);
        }

        float s[8][4];
#pragma unroll
        for (int j = 0; j < 8; j++)
#pragma unroll
            for (int e = 0; e < 4; e++) s[j][e] = 0.f;
#pragma unroll
        for (int kk = 0; kk < 4; kk++) {
#pragma unroll
            for (int j = 0; j < 8; j++) {
                uint2 kb = Kc[kk * 257 + (j * 8 + mu) * 4 + la];
                mma_bf16(s[j], qf[kk], kb.x, kb.y);
            }
        }

        float mx0 = -1e30f, mx1 = -1e30f;
#pragma unroll
        for (int j = 0; j < 8; j++) {
            mx0 = fmaxf(mx0, fmaxf(s[j][0], s[j][1]));
            mx1 = fmaxf(mx1, fmaxf(s[j][2], s[j][3]));
        }
        mx0 = fmaxf(mx0, __shfl_xor_sync(0xffffffffu, mx0, 1));
        mx0 = fmaxf(mx0, __shfl_xor_sync(0xffffffffu, mx0, 2));
        mx1 = fmaxf(mx1, __shfl_xor_sync(0xffffffffu, mx1, 1));
        mx1 = fmaxf(mx1, __shfl_xor_sync(0xffffffffu, mx1, 2));
        const float nm0 = fmaxf(m0, mx0), nm1 = fmaxf(m1, mx1);
        float sum0 = 0.f, sum1 = 0.f;
#pragma unroll
        for (int j = 0; j < 8; j++) {
            s[j][0] = exp2f(s[j][0] - nm0);
            s[j][1] = exp2f(s[j][1] - nm0);
            s[j][2] = exp2f(s[j][2] - nm1);
            s[j][3] = exp2f(s[j][3] - nm1);
            sum0 += s[j][0] + s[j][1];
            sum1 += s[j][2] + s[j][3];
        }
        sum0 += __shfl_xor_sync(0xffffffffu, sum0, 1);
        sum0 += __shfl_xor_sync(0xffffffffu, sum0, 2);
        sum1 += __shfl_xor_sync(0xffffffffu, sum1, 1);
        sum1 += __shfl_xor_sync(0xffffffffu, sum1, 2);
        const float sc0 = exp2f(m0 - nm0), sc1 = exp2f(m1 - nm1);
#pragma unroll
        for (int j = 0; j < 8; j++) {
            acc[j][0] *= sc0; acc[j][1] *= sc0;
            acc[j][2] *= sc1; acc[j][3] *= sc1;
        }
        l0 = l0 * sc0 + sum0; l1 = l1 * sc1 + sum1;
        m0 = nm0; m1 = nm1;

        uint32_t pf[4][4];
#pragma unroll
        for (int kk = 0; kk < 4; kk++) {
            pf[kk][0] = packbf(s[2 * kk][0],     s[2 * kk][1]);
            pf[kk][1] = packbf(s[2 * kk][2],     s[2 * kk][3]);
            pf[kk][2] = packbf(s[2 * kk + 1][0], s[2 * kk + 1][1]);
            pf[kk][3] = packbf(s[2 * kk + 1][2], s[2 * kk + 1][3]);
        }

#pragma unroll
        for (int kk = 0; kk < 4; kk++) {
#pragma unroll
            for (int j = 0; j < 8; j++) {
                uint2 vb = Vc[kk * 257 + (j * 8 + mu) * 4 + la];
                mma_bf16(acc[j], pf[kk], vb.x, vb.y);
            }
        }

        if (more) {
            uint2* kd = fsm + ((kt + 1) & 1) * FKB + kdst_i;
            kd[0] = make_uint2(ku0.x, ku1.x); kd[1] = make_uint2(ku0.y, ku1.y);
            kd[2] = make_uint2(ku0.z, ku1.z); kd[3] = make_uint2(ku0.w, ku1.w);
            uint2* vdp = fsm + 2 * FKB + ((kt + 1) & 1) * FKB + vdst_i;
            vdp[0] = make_uint2(vu0.x, vu1.x); vdp[1] = make_uint2(vu0.y, vu1.y);
            vdp[2] = make_uint2(vu0.z, vu1.z); vdp[3] = make_uint2(vu0.w, vu1.w);
        }
        __syncthreads();
    }

    // ---- epilogue: normalize, write bf16 [B,S,E] ----
    const float i0 = 1.f / l0, i1 = 1.f / l1;
    const int row_a = q0 + wid * 16 + mu;
    const int row_b = row_a + 8;
    __nv_bfloat16* oa = &g_attnb[((size_t)b * S_LEN + row_a) * E_DIM + h * DK_];
    __nv_bfloat16* ob = &g_attnb[((size_t)b * S_LEN + row_b) * E_DIM + h * DK_];
#pragma unroll
    for (int j = 0; j < 8; j++) {
        const int c = j * 8 + 2 * la;
        *(uint32_t*)&oa[c] = packbf(acc[j][0] * i0, acc[j][1] * i0);
        *(uint32_t*)&ob[c] = packbf(acc[j][2] * i1, acc[j][3] * i1);
    }
}

// ======================================================================
// Fused LN1 + quantum FFN + LN2 — float4 vectorized (passing).
// ======================================================================
__global__ __launch_bounds__(256) void ln_fused(const float* __restrict__ x,
                                                const float* __restrict__ g1,
                                                const float* __restrict__ be1,
                                                const float* __restrict__ g2,
                                                const float* __restrict__ be2,
                                                const float* __restrict__ theta,
                                                const float* __restrict__ w1,
                                                const float* __restrict__ b1s,
                                                float* __restrict__ out)
{
    const int row = blockIdx.x;
    const int tid = threadIdx.x;
    const float* xr = x + (size_t)row * E_DIM;
    const float* pr = g_proj + (size_t)row * E_DIM;

    __shared__ float red[16];
    __shared__ float sx1[8];

    float4 xv = *(const float4*)&xr[tid * 4];
    float4 pv = *(const float4*)&pr[tid * 4];
    float v[4] = {xv.x + pv.x, xv.y + pv.y, xv.z + pv.z, xv.w + pv.w};

    float s = 0.f, ss = 0.f;
#pragma unroll
    for (int i = 0; i < 4; i++) { s += v[i]; ss += v[i] * v[i]; }
#pragma unroll
    for (int o = 16; o > 0; o >>= 1) {
        s  += __shfl_xor_sync(0xffffffffu, s, o);
        ss += __shfl_xor_sync(0xffffffffu, ss, o);
    }
    if ((tid & 31) == 0) { red[tid >> 5] = s; red[8 + (tid >> 5)] = ss; }
    __syncthreads();
    s = 0.f; ss = 0.f;
#pragma unroll
    for (int w = 0; w < 8; w++) { s += red[w]; ss += red[8 + w]; }
    float mean = s * (1.f / E_DIM);
    float var  = ss * (1.f / E_DIM) - mean * mean;
    float rs = rsqrtf(var + 1e-5f);

    float4 g1v = *(const float4*)&g1[tid * 4];
    float4 b1v = *(const float4*)&be1[tid * 4];
    float x1[4];
    x1[0] = (v[0] - mean) * rs * g1v.x + b1v.x;
    x1[1] = (v[1] - mean) * rs * g1v.y + b1v.y;
    x1[2] = (v[2] - mean) * rs * g1v.z + b1v.z;
    x1[3] = (v[3] - mean) * rs * g1v.w + b1v.w;
    if (tid < 2) {
#pragma unroll
        for (int i = 0; i < 4; i++) sx1[tid * 4 + i] = x1[i];
    }
    __syncthreads();

    float f = b1s[0];
#pragma unroll
    for (int q = 0; q < 8; q++) f += __cosf(sx1[q]) * __cosf(theta[q]) * w1[q];

    float y[4];
    s = 0.f; ss = 0.f;
#pragma unroll
    for (int i = 0; i < 4; i++) { y[i] = x1[i] + f; s += y[i]; ss += y[i] * y[i]; }
#pragma unroll
    for (int o = 16; o > 0; o >>= 1) {
        s  += __shfl_xor_sync(0xffffffffu, s, o);
        ss += __shfl_xor_sync(0xffffffffu, ss, o);
    }
    if ((tid & 31) == 0) { red[tid >> 5] = s; red[8 + (tid >> 5)] = ss; }
    __syncthreads();
    s = 0.f; ss = 0.f;
#pragma unroll
    for (int w = 0; w < 8; w++) { s += red[w]; ss += red[8 + w]; }
    float mean2 = s * (1.f / E_DIM);
    float var2  = ss * (1.f / E_DIM) - mean2 * mean2;
    float rs2 = rsqrtf(var2 + 1e-5f);

    float4 g2v = *(const float4*)&g2[tid * 4];
    float4 b2v = *(const float4*)&be2[tid * 4];
    float4 ov;
    ov.x = (y[0] - mean2) * rs2 * g2v.x + b2v.x;
    ov.y = (y[1] - mean2) * rs2 * g2v.y + b2v.y;
    ov.z = (y[2] - mean2) * rs2 * g2v.z + b2v.z;
    ov.w = (y[3] - mean2) * rs2 * g2v.w + b2v.w;
    *(float4*)&out[(size_t)row * E_DIM + tid * 4] = ov;
}

// ======================================================================
extern "C" void kernel_launch(void* const* d_in, const int* in_sizes, int n_in,
                              void* d_out, int out_size)
{
    const float* x      = (const float*)d_in[0];
    const float* w_qkv  = (const float*)d_in[1];
    const float* w_comb = (const float*)d_in[2];
    const float* b_comb = (const float*)d_in[3];
    const float* gamma1 = (const float*)d_in[4];
    const float* beta1  = (const float*)d_in[5];
    const float* gamma2 = (const float*)d_in[6];
    const float* beta2  = (const float*)d_in[7];
    const float* theta  = (const float*)d_in[8];
    const float* w1     = (const float*)d_in[9];
    const float* b1     = (const float*)d_in[10];

    __nv_bfloat16* xb_p;  cudaGetSymbolAddress((void**)&xb_p, g_xb);
    __nv_bfloat16* wqb_p; cudaGetSymbolAddress((void**)&wqb_p, g_wqb);
    __nv_bfloat16* wcb_p; cudaGetSymbolAddress((void**)&wcb_p, g_wcb);

    cudaFuncSetAttribute(gemm_bf16<0>, cudaFuncAttributeMaxDynamicSharedMemorySize,
                         GEMM_SMEM_BYTES);
    cudaFuncSetAttribute(gemm_bf16<1>, cudaFuncAttributeMaxDynamicSharedMemorySize,
                         GEMM_SMEM_BYTES);
    cudaFuncSetAttribute(flash_bf16, cudaFuncAttributeMaxDynamicSharedMemorySize,
                         FLASH_SMEM_BYTES);

    conv_bf16<<<(M_TOK * K_DIM / 8 + 255) / 256, 256>>>(x, xb_p, M_TOK * K_DIM / 8);
    conv_bf16<<<(N_QKV * K_DIM / 8 + 255) / 256, 256>>>(w_qkv, wqb_p, N_QKV * K_DIM / 8);
    conv_bf16<<<(E_DIM * K_DIM / 8 + 255) / 256, 256>>>(w_comb, wcb_p, E_DIM * K_DIM / 8);

    gemm_bf16<0><<<dim3(N_QKV / 128, M_TOK / 128), 256, GEMM_SMEM_BYTES>>>(nullptr);
    flash_bf16<<<dim3(S_LEN / 128, H_NUM, B_SZ), 256, FLASH_SMEM_BYTES>>>();
    gemm_bf16<1><<<dim3(E_DIM / 128, M_TOK / 128), 256, GEMM_SMEM_BYTES>>>(b_comb);
    ln_fused<<<M_TOK, 256>>>(x, gamma1, beta1, gamma2, beta2, theta, w1, b1,
                             (float*)d_out);
}

// round 10
// speedup vs baseline: 5.7414x; 1.0056x over previous
#include <cuda_runtime.h>
#include <cuda_bf16.h>
#include <cstdint>
#include <math.h>

// ---------------- problem constants ----------------
#define E_DIM  1024
#define H_NUM  16
#define DK_    64
#define B_SZ   2
#define S_LEN  2048
#define M_TOK  (B_SZ * S_LEN)
#define N_QKV  (3 * E_DIM)
#define K_DIM  1024

#define QSCALE (0.125f * 1.44269504088896f)   // 1/sqrt(dk) * log2(e)

// ---------------- device scratch (alloc-free) ----------------
__device__ __align__(16) __nv_bfloat16 g_xb[M_TOK * K_DIM];
__device__ __align__(16) __nv_bfloat16 g_wqb[N_QKV * K_DIM];
__device__ __align__(16) __nv_bfloat16 g_wcb[E_DIM * K_DIM];
__device__ __align__(16) __nv_bfloat16 g_qb[B_SZ * H_NUM * S_LEN * DK_];
__device__ __align__(16) __nv_bfloat16 g_kb[B_SZ * H_NUM * S_LEN * DK_];
__device__ __align__(16) __nv_bfloat16 g_vTb[B_SZ * H_NUM * DK_ * S_LEN];
__device__ __align__(16) __nv_bfloat16 g_attnb[M_TOK * E_DIM];
__device__ float g_proj[M_TOK * E_DIM];

__device__ __forceinline__ uint32_t packbf(float lo, float hi) {
    uint32_t r;
    asm("cvt.rn.bf16x2.f32 %0, %1, %2;" : "=r"(r) : "f"(hi), "f"(lo));
    return r;
}
__device__ __forceinline__ void mma_bf16(float c[4], const uint32_t a[4],
                                         const uint32_t b0, const uint32_t b1) {
    asm volatile(
        "mma.sync.aligned.m16n8k16.row.col.f32.bf16.bf16.f32 "
        "{%0,%1,%2,%3}, {%4,%5,%6,%7}, {%8,%9}, {%0,%1,%2,%3};"
        : "+f"(c[0]), "+f"(c[1]), "+f"(c[2]), "+f"(c[3])
        : "r"(a[0]), "r"(a[1]), "r"(a[2]), "r"(a[3]), "r"(b0), "r"(b1));
}
__device__ __forceinline__ void ldm_x4(uint32_t& r0, uint32_t& r1,
                                       uint32_t& r2, uint32_t& r3, uint32_t a) {
    asm volatile("ldmatrix.sync.aligned.m8n8.x4.shared.b16 {%0,%1,%2,%3}, [%4];"
                 : "=r"(r0), "=r"(r1), "=r"(r2), "=r"(r3) : "r"(a));
}
__device__ __forceinline__ void cp16(uint32_t dst, const void* src) {
    asm volatile("cp.async.cg.shared.global [%0], [%1], 16;"
                 :: "r"(dst), "l"(src));
}
#define CP_COMMIT() asm volatile("cp.async.commit_group;")
#define CP_WAIT1()  asm volatile("cp.async.wait_group 1;")

// ======================================================================
// fp32 -> bf16 bulk convert
// ======================================================================
__global__ __launch_bounds__(256) void conv_bf16(const float* __restrict__ src,
                                                 __nv_bfloat16* __restrict__ dst,
                                                 int n8)
{
    int i = blockIdx.x * 256 + threadIdx.x;
    if (i >= n8) return;
    float4 a = *(const float4*)&src[i * 8];
    float4 b = *(const float4*)&src[i * 8 + 4];
    uint4 o = make_uint4(packbf(a.x, a.y), packbf(a.z, a.w),
                         packbf(b.x, b.y), packbf(b.z, b.w));
    *(uint4*)&dst[i * 8] = o;
}

// ======================================================================
// bf16 GEMM, cp.async 3-stage pipeline + ldmatrix fragments.
// C[M,N] = A[M,K] @ W[N,K]^T. CTA 128x128, BK=32, 8 warps (2m x 4n).
// Smem per stage: A tile 128 rows x 80B (64B data + 16B pad), then B same.
//   80B stride => (5*row + chunk) mod 8 distinct over any 8 rows:
//   conflict-free ldmatrix AND 16B-aligned cp.async.
// MODE 0: A=g_xb, W=g_wqb -> g_qb(xQSCALE)/g_kb/g_vTb
// MODE 1: A=g_attnb, W=g_wcb, +bias -> fp32 g_proj
// ======================================================================
#define ROWB 80
#define MATB (128 * ROWB)                  // 10240
#define STAGEB (2 * MATB)                  // 20480
#define NSTAGE 3
#define GEMM_SMEM_BYTES (NSTAGE * STAGEB)  // 61440

template <int MODE>
__global__ __launch_bounds__(256) void gemm_cp(const float* __restrict__ bias)
{
    extern __shared__ char sm[];
    const uint32_t smbase = (uint32_t)__cvta_generic_to_shared(sm);

    const __nv_bfloat16* __restrict__ A = (MODE == 1) ? g_attnb : g_xb;
    const __nv_bfloat16* __restrict__ W = (MODE == 1) ? g_wcb : g_wqb;

    const int tid = threadIdx.x;
    const int wid = tid >> 5;
    const int lane = tid & 31;
    const int mu = lane >> 2;
    const int la = lane & 3;
    const int warp_m = wid & 1;
    const int warp_n = wid >> 1;
    const int m0 = blockIdx.y * 128;
    const int n0 = blockIdx.x * 128;

    // staging: thread t -> row tid>>1, chunks 2*(tid&1), +1 of A and B
    const int st_row = tid >> 1;
    const int st_c   = (tid & 1) * 2;
    const __nv_bfloat16* asrc = &A[(size_t)(m0 + st_row) * K_DIM + st_c * 8];
    const __nv_bfloat16* wsrc = &W[(size_t)(n0 + st_row) * K_DIM + st_c * 8];
    const uint32_t st_off = (uint32_t)(st_row * ROWB + st_c * 16);

    // ldmatrix source addresses (row = base + lane&15, chunk += lane>>4)
    const int lrow = lane & 15;
    const int lchunk = lane >> 4;

    float acc[4][4][4];
#pragma unroll
    for (int mt = 0; mt < 4; mt++)
#pragma unroll
        for (int nt = 0; nt < 4; nt++)
#pragma unroll
            for (int e = 0; e < 4; e++) acc[mt][nt][e] = 0.f;

    const int NK = K_DIM / 32;             // 32

    // ---- prologue: issue stages 0,1 ----
#pragma unroll
    for (int t = 0; t < NSTAGE - 1; t++) {
        uint32_t ad = smbase + t * STAGEB + st_off;
        cp16(ad,      asrc + t * 32);
        cp16(ad + 16, asrc + t * 32 + 8);
        cp16(ad + MATB,      wsrc + t * 32);
        cp16(ad + MATB + 16, wsrc + t * 32 + 8);
        CP_COMMIT();
    }

    for (int t = 0; t < NK; t++) {
        CP_WAIT1();                        // stage t landed
        __syncthreads();

        // issue stage t+2 (or empty group to keep the count uniform)
        if (t + NSTAGE - 1 < NK) {
            const int tt = t + NSTAGE - 1;
            uint32_t ad = smbase + (tt % NSTAGE) * STAGEB + st_off;
            cp16(ad,      asrc + tt * 32);
            cp16(ad + 16, asrc + tt * 32 + 8);
            cp16(ad + MATB,      wsrc + tt * 32);
            cp16(ad + MATB + 16, wsrc + tt * 32 + 8);
        }
        CP_COMMIT();

        const uint32_t abase = smbase + (t % NSTAGE) * STAGEB;
        const uint32_t bbase = abase + MATB;

#pragma unroll
        for (int kk = 0; kk < 2; kk++) {
            uint32_t afr[4][4];
#pragma unroll
            for (int mt = 0; mt < 4; mt++) {
                const int row = warp_m * 64 + mt * 16 + lrow;
                ldm_x4(afr[mt][0], afr[mt][1], afr[mt][2], afr[mt][3],
                       abase + row * ROWB + (kk * 2 + lchunk) * 16);
            }
            uint32_t bfr[4][2];
#pragma unroll
            for (int np = 0; np < 2; np++) {
                const int row = warp_n * 32 + np * 16 + lrow;
                uint32_t b0, b1, b2, b3;
                ldm_x4(b0, b1, b2, b3,
                       bbase + row * ROWB + (kk * 2 + lchunk) * 16);
                bfr[2 * np][0] = b0;     bfr[2 * np][1] = b2;
                bfr[2 * np + 1][0] = b1; bfr[2 * np + 1][1] = b3;
            }
#pragma unroll
            for (int mt = 0; mt < 4; mt++)
#pragma unroll
                for (int nt = 0; nt < 4; nt++)
                    mma_bf16(acc[mt][nt], afr[mt], bfr[nt][0], bfr[nt][1]);
        }
        __syncthreads();                   // all reads of stage t done
    }

    // ---- epilogue ----
#pragma unroll
    for (int mt = 0; mt < 4; mt++) {
        const int m_lo = m0 + warp_m * 64 + mt * 16 + mu;
        const int m_hi = m_lo + 8;
#pragma unroll
        for (int nt = 0; nt < 4; nt++) {
            const int n = n0 + warp_n * 32 + nt * 8 + 2 * la;
            if (MODE == 0) {
                const int which = n >> 10;
                const int h = (n >> 6) & 15;
                const int d0 = n & 63;
                const int b = m_lo >> 11;
                const int s_lo = m_lo & 2047, s_hi = m_hi & 2047;
                if (which == 0) {
                    size_t base = (((size_t)(b * H_NUM + h)) * S_LEN);
                    *(uint32_t*)&g_qb[(base + s_lo) * DK_ + d0] =
                        packbf(acc[mt][nt][0] * QSCALE, acc[mt][nt][1] * QSCALE);
                    *(uint32_t*)&g_qb[(base + s_hi) * DK_ + d0] =
                        packbf(acc[mt][nt][2] * QSCALE, acc[mt][nt][3] * QSCALE);
                } else if (which == 1) {
                    size_t base = (((size_t)(b * H_NUM + h)) * S_LEN);
                    *(uint32_t*)&g_kb[(base + s_lo) * DK_ + d0] =
                        packbf(acc[mt][nt][0], acc[mt][nt][1]);
                    *(uint32_t*)&g_kb[(base + s_hi) * DK_ + d0] =
                        packbf(acc[mt][nt][2], acc[mt][nt][3]);
                } else {
                    size_t base = (((size_t)(b * H_NUM + h)) * DK_ + d0) * S_LEN;
                    g_vTb[base + s_lo]          = __float2bfloat16_rn(acc[mt][nt][0]);
                    g_vTb[base + S_LEN + s_lo]  = __float2bfloat16_rn(acc[mt][nt][1]);
                    g_vTb[base + s_hi]          = __float2bfloat16_rn(acc[mt][nt][2]);
                    g_vTb[base + S_LEN + s_hi]  = __float2bfloat16_rn(acc[mt][nt][3]);
                }
            } else {
                const float b0 = bias[n], b1 = bias[n + 1];
                *(float2*)&g_proj[(size_t)m_lo * E_DIM + n] =
                    make_float2(acc[mt][nt][0] + b0, acc[mt][nt][1] + b1);
                *(float2*)&g_proj[(size_t)m_hi * E_DIM + n] =
                    make_float2(acc[mt][nt][2] + b0, acc[mt][nt][3] + b1);
            }
        }
    }
}

// ======================================================================
// Flash attention, bf16 m16n8k16, register-resident P (unchanged, passing).
// ======================================================================
#define FKB 1028
#define FLASH_U2 (4 * FKB + 128 * 20)
#define FLASH_SMEM_BYTES (FLASH_U2 * 8)

__global__ __launch_bounds__(256, 2) void flash_bf16()
{
    extern __shared__ uint2 fsm[];
    uint2* Qp = fsm + 4 * FKB;

    const int tid = threadIdx.x;
    const int wid = tid >> 5;
    const int lane = tid & 31;
    const int mu = lane >> 2;
    const int la = lane & 3;
    const int b = blockIdx.z, h = blockIdx.y;
    const int q0 = blockIdx.x * 128;
    const size_t hoff = ((size_t)(b * H_NUM + h)) * S_LEN * DK_;

    const int kkk = tid & 3, kkey = tid >> 2;
    const __nv_bfloat16* ksrc = g_kb + hoff + (size_t)kkey * DK_ + kkk * 16;
    const int vkk = tid & 3, vd = tid >> 2;
    const __nv_bfloat16* vsrc = g_vTb + hoff + (size_t)vd * S_LEN + vkk * 16;
    const int kdst_i = kkk * 257 + kkey * 4;
    const int vdst_i = vkk * 257 + vd * 4;

#pragma unroll
    for (int it = 0; it < 2; it++) {
        int item = tid + it * 256;
        int row = item >> 2, kk = item & 3;
        const __nv_bfloat16* qs = g_qb + hoff + (size_t)(q0 + row) * DK_ + kk * 16;
        uint4 u0 = *(const uint4*)qs;
        uint4 u1 = *(const uint4*)(qs + 8);
        uint2* dst = Qp + row * 20 + kk * 4;
        dst[0] = make_uint2(u0.x, u1.x);
        dst[1] = make_uint2(u0.y, u1.y);
        dst[2] = make_uint2(u0.z, u1.z);
        dst[3] = make_uint2(u0.w, u1.w);
    }
    {
        uint4 k0a = *(const uint4*)ksrc;
        uint4 k0b = *(const uint4*)(ksrc + 8);
        uint4 v0a = *(const uint4*)vsrc;
        uint4 v0b = *(const uint4*)(vsrc + 8);
        uint2* kd = fsm + kdst_i;
        kd[0] = make_uint2(k0a.x, k0b.x); kd[1] = make_uint2(k0a.y, k0b.y);
        kd[2] = make_uint2(k0a.z, k0b.z); kd[3] = make_uint2(k0a.w, k0b.w);
        uint2* vdp = fsm + 2 * FKB + vdst_i;
        vdp[0] = make_uint2(v0a.x, v0b.x); vdp[1] = make_uint2(v0a.y, v0b.y);
        vdp[2] = make_uint2(v0a.z, v0b.z); vdp[3] = make_uint2(v0a.w, v0b.w);
    }
    __syncthreads();

    uint32_t qf[4][4];
    {
        const int r0 = wid * 16 + mu;
#pragma unroll
        for (int kk = 0; kk < 4; kk++) {
            uint2 qa = Qp[r0 * 20 + kk * 4 + la];
            uint2 qb = Qp[(r0 + 8) * 20 + kk * 4 + la];
            qf[kk][0] = qa.x; qf[kk][1] = qb.x;
            qf[kk][2] = qa.y; qf[kk][3] = qb.y;
        }
    }

    float m0 = -1e30f, m1 = -1e30f, l0 = 0.f, l1 = 0.f;
    float acc[8][4];
#pragma unroll
    for (int j = 0; j < 8; j++)
#pragma unroll
        for (int e = 0; e < 4; e++) acc[j][e] = 0.f;

    const int NCH = S_LEN / 64;
    for (int kt = 0; kt < NCH; kt++) {
        const uint2* Kc = fsm + (kt & 1) * FKB;
        const uint2* Vc = fsm + 2 * FKB + (kt & 1) * FKB;

        uint4 ku0, ku1, vu0, vu1;
        const bool more = (kt + 1 < NCH);
        if (more) {
            const __nv_bfloat16* ks = ksrc + (size_t)(kt + 1) * 64 * DK_;
            const __nv_bfloat16* vs = vsrc + (size_t)(kt + 1) * 64;
            ku0 = *(const uint4*)ks; ku1 = *(const uint4*)(ks + 8);
            vu0 = *(const uint4*)vs; vu1 = *(const uint4*)(vs + 8);
        }

        float s[8][4];
#pragma unroll
        for (int j = 0; j < 8; j++)
#pragma unroll
            for (int e = 0; e < 4; e++) s[j][e] = 0.f;
#pragma unroll
        for (int kk = 0; kk < 4; kk++) {
#pragma unroll
            for (int j = 0; j < 8; j++) {
                uint2 kb = Kc[kk * 257 + (j * 8 + mu) * 4 + la];
                mma_bf16(s[j], qf[kk], kb.x, kb.y);
            }
        }

        float mx0 = -1e30f, mx1 = -1e30f;
#pragma unroll
        for (int j = 0; j < 8; j++) {
            mx0 = fmaxf(mx0, fmaxf(s[j][0], s[j][1]));
            mx1 = fmaxf(mx1, fmaxf(s[j][2], s[j][3]));
        }
        mx0 = fmaxf(mx0, __shfl_xor_sync(0xffffffffu, mx0, 1));
        mx0 = fmaxf(mx0, __shfl_xor_sync(0xffffffffu, mx0, 2));
        mx1 = fmaxf(mx1, __shfl_xor_sync(0xffffffffu, mx1, 1));
        mx1 = fmaxf(mx1, __shfl_xor_sync(0xffffffffu, mx1, 2));
        const float nm0 = fmaxf(m0, mx0), nm1 = fmaxf(m1, mx1);
        float sum0 = 0.f, sum1 = 0.f;
#pragma unroll
        for (int j = 0; j < 8; j++) {
            s[j][0] = exp2f(s[j][0] - nm0);
            s[j][1] = exp2f(s[j][1] - nm0);
            s[j][2] = exp2f(s[j][2] - nm1);
            s[j][3] = exp2f(s[j][3] - nm1);
            sum0 += s[j][0] + s[j][1];
            sum1 += s[j][2] + s[j][3];
        }
        sum0 += __shfl_xor_sync(0xffffffffu, sum0, 1);
        sum0 += __shfl_xor_sync(0xffffffffu, sum0, 2);
        sum1 += __shfl_xor_sync(0xffffffffu, sum1, 1);
        sum1 += __shfl_xor_sync(0xffffffffu, sum1, 2);
        const float sc0 = exp2f(m0 - nm0), sc1 = exp2f(m1 - nm1);
#pragma unroll
        for (int j = 0; j < 8; j++) {
            acc[j][0] *= sc0; acc[j][1] *= sc0;
            acc[j][2] *= sc1; acc[j][3] *= sc1;
        }
        l0 = l0 * sc0 + sum0; l1 = l1 * sc1 + sum1;
        m0 = nm0; m1 = nm1;

        uint32_t pf[4][4];
#pragma unroll
        for (int kk = 0; kk < 4; kk++) {
            pf[kk][0] = packbf(s[2 * kk][0],     s[2 * kk][1]);
            pf[kk][1] = packbf(s[2 * kk][2],     s[2 * kk][3]);
            pf[kk][2] = packbf(s[2 * kk + 1][0], s[2 * kk + 1][1]);
            pf[kk][3] = packbf(s[2 * kk + 1][2], s[2 * kk + 1][3]);
        }

#pragma unroll
        for (int kk = 0; kk < 4; kk++) {
#pragma unroll
            for (int j = 0; j < 8; j++) {
                uint2 vb = Vc[kk * 257 + (j * 8 + mu) * 4 + la];
                mma_bf16(acc[j], pf[kk], vb.x, vb.y);
            }
        }

        if (more) {
            uint2* kd = fsm + ((kt + 1) & 1) * FKB + kdst_i;
            kd[0] = make_uint2(ku0.x, ku1.x); kd[1] = make_uint2(ku0.y, ku1.y);
            kd[2] = make_uint2(ku0.z, ku1.z); kd[3] = make_uint2(ku0.w, ku1.w);
            uint2* vdp = fsm + 2 * FKB + ((kt + 1) & 1) * FKB + vdst_i;
            vdp[0] = make_uint2(vu0.x, vu1.x); vdp[1] = make_uint2(vu0.y, vu1.y);
            vdp[2] = make_uint2(vu0.z, vu1.z); vdp[3] = make_uint2(vu0.w, vu1.w);
        }
        __syncthreads();
    }

    const float i0 = 1.f / l0, i1 = 1.f / l1;
    const int row_a = q0 + wid * 16 + mu;
    const int row_b = row_a + 8;
    __nv_bfloat16* oa = &g_attnb[((size_t)b * S_LEN + row_a) * E_DIM + h * DK_];
    __nv_bfloat16* ob = &g_attnb[((size_t)b * S_LEN + row_b) * E_DIM + h * DK_];
#pragma unroll
    for (int j = 0; j < 8; j++) {
        const int c = j * 8 + 2 * la;
        *(uint32_t*)&oa[c] = packbf(acc[j][0] * i0, acc[j][1] * i0);
        *(uint32_t*)&ob[c] = packbf(acc[j][2] * i1, acc[j][3] * i1);
    }
}

// ======================================================================
// Fused LN1 + quantum FFN + LN2 (unchanged, passing).
// ======================================================================
__global__ __launch_bounds__(256) void ln_fused(const float* __restrict__ x,
                                                const float* __restrict__ g1,
                                                const float* __restrict__ be1,
                                                const float* __restrict__ g2,
                                                const float* __restrict__ be2,
                                                const float* __restrict__ theta,
                                                const float* __restrict__ w1,
                                                const float* __restrict__ b1s,
                                                float* __restrict__ out)
{
    const int row = blockIdx.x;
    const int tid = threadIdx.x;
    const float* xr = x + (size_t)row * E_DIM;
    const float* pr = g_proj + (size_t)row * E_DIM;

    __shared__ float red[16];
    __shared__ float sx1[8];

    float4 xv = *(const float4*)&xr[tid * 4];
    float4 pv = *(const float4*)&pr[tid * 4];
    float v[4] = {xv.x + pv.x, xv.y + pv.y, xv.z + pv.z, xv.w + pv.w};

    float s = 0.f, ss = 0.f;
#pragma unroll
    for (int i = 0; i < 4; i++) { s += v[i]; ss += v[i] * v[i]; }
#pragma unroll
    for (int o = 16; o > 0; o >>= 1) {
        s  += __shfl_xor_sync(0xffffffffu, s, o);
        ss += __shfl_xor_sync(0xffffffffu, ss, o);
    }
    if ((tid & 31) == 0) { red[tid >> 5] = s; red[8 + (tid >> 5)] = ss; }
    __syncthreads();
    s = 0.f; ss = 0.f;
#pragma unroll
    for (int w = 0; w < 8; w++) { s += red[w]; ss += red[8 + w]; }
    float mean = s * (1.f / E_DIM);
    float var  = ss * (1.f / E_DIM) - mean * mean;
    float rs = rsqrtf(var + 1e-5f);

    float4 g1v = *(const float4*)&g1[tid * 4];
    float4 b1v = *(const float4*)&be1[tid * 4];
    float x1[4];
    x1[0] = (v[0] - mean) * rs * g1v.x + b1v.x;
    x1[1] = (v[1] - mean) * rs * g1v.y + b1v.y;
    x1[2] = (v[2] - mean) * rs * g1v.z + b1v.z;
    x1[3] = (v[3] - mean) * rs * g1v.w + b1v.w;
    if (tid < 2) {
#pragma unroll
        for (int i = 0; i < 4; i++) sx1[tid * 4 + i] = x1[i];
    }
    __syncthreads();

    float f = b1s[0];
#pragma unroll
    for (int q = 0; q < 8; q++) f += __cosf(sx1[q]) * __cosf(theta[q]) * w1[q];

    float y[4];
    s = 0.f; ss = 0.f;
#pragma unroll
    for (int i = 0; i < 4; i++) { y[i] = x1[i] + f; s += y[i]; ss += y[i] * y[i]; }
#pragma unroll
    for (int o = 16; o > 0; o >>= 1) {
        s  += __shfl_xor_sync(0xffffffffu, s, o);
        ss += __shfl_xor_sync(0xffffffffu, ss, o);
    }
    if ((tid & 31) == 0) { red[tid >> 5] = s; red[8 + (tid >> 5)] = ss; }
    __syncthreads();
    s = 0.f; ss = 0.f;
#pragma unroll
    for (int w = 0; w < 8; w++) { s += red[w]; ss += red[8 + w]; }
    float mean2 = s * (1.f / E_DIM);
    float var2  = ss * (1.f / E_DIM) - mean2 * mean2;
    float rs2 = rsqrtf(var2 + 1e-5f);

    float4 g2v = *(const float4*)&g2[tid * 4];
    float4 b2v = *(const float4*)&be2[tid * 4];
    float4 ov;
    ov.x = (y[0] - mean2) * rs2 * g2v.x + b2v.x;
    ov.y = (y[1] - mean2) * rs2 * g2v.y + b2v.y;
    ov.z = (y[2] - mean2) * rs2 * g2v.z + b2v.z;
    ov.w = (y[3] - mean2) * rs2 * g2v.w + b2v.w;
    *(float4*)&out[(size_t)row * E_DIM + tid * 4] = ov;
}

// ======================================================================
extern "C" void kernel_launch(void* const* d_in, const int* in_sizes, int n_in,
                              void* d_out, int out_size)
{
    const float* x      = (const float*)d_in[0];
    const float* w_qkv  = (const float*)d_in[1];
    const float* w_comb = (const float*)d_in[2];
    const float* b_comb = (const float*)d_in[3];
    const float* gamma1 = (const float*)d_in[4];
    const float* beta1  = (const float*)d_in[5];
    const float* gamma2 = (const float*)d_in[6];
    const float* beta2  = (const float*)d_in[7];
    const float* theta  = (const float*)d_in[8];
    const float* w1     = (const float*)d_in[9];
    const float* b1     = (const float*)d_in[10];

    __nv_bfloat16* xb_p;  cudaGetSymbolAddress((void**)&xb_p, g_xb);
    __nv_bfloat16* wqb_p; cudaGetSymbolAddress((void**)&wqb_p, g_wqb);
    __nv_bfloat16* wcb_p; cudaGetSymbolAddress((void**)&wcb_p, g_wcb);

    cudaFuncSetAttribute(gemm_cp<0>, cudaFuncAttributeMaxDynamicSharedMemorySize,
                         GEMM_SMEM_BYTES);
    cudaFuncSetAttribute(gemm_cp<1>, cudaFuncAttributeMaxDynamicSharedMemorySize,
                         GEMM_SMEM_BYTES);
    cudaFuncSetAttribute(flash_bf16, cudaFuncAttributeMaxDynamicSharedMemorySize,
                         FLASH_SMEM_BYTES);

    conv_bf16<<<(M_TOK * K_DIM / 8 + 255) / 256, 256>>>(x, xb_p, M_TOK * K_DIM / 8);
    conv_bf16<<<(N_QKV * K_DIM / 8 + 255) / 256, 256>>>(w_qkv, wqb_p, N_QKV * K_DIM / 8);
    conv_bf16<<<(E_DIM * K_DIM / 8 + 255) / 256, 256>>>(w_comb, wcb_p, E_DIM * K_DIM / 8);

    gemm_cp<0><<<dim3(N_QKV / 128, M_TOK / 128), 256, GEMM_SMEM_BYTES>>>(nullptr);
    flash_bf16<<<dim3(S_LEN / 128, H_NUM, B_SZ), 256, FLASH_SMEM_BYTES>>>();
    gemm_cp<1><<<dim3(E_DIM / 128, M_TOK / 128), 256, GEMM_SMEM_BYTES>>>(b_comb);
    ln_fused<<<M_TOK, 256>>>(x, gamma1, beta1, gamma2, beta2, theta, w1, b1,
                             (float*)d_out);
}